// round 3
// baseline (speedup 1.0000x reference)
#include <cuda_runtime.h>
#include <math.h>

#define BB 2
#define CH 96
#define FGC 192
#define HH 64
#define WW 64
#define LL 4096
#define NST 16
#define RKN 6
#define KD 4
#define DBLR 38

// ---------------- scratch (static device globals; no allocations) ----------------
__device__ float g_y[BB*CH*LL];
__device__ float g_dr[BB*CH*LL];
__device__ float g_xz[BB*2*CH*LL];
__device__ float g_xc[BB*CH*LL];
__device__ float g_xs[BB*KD*CH*LL];
__device__ float g_dbl[BB*KD*DBLR*LL];
__device__ float g_Bt[BB*KD*LL*NST];
__device__ float g_Ct[BB*KD*LL*NST];
__device__ float g_delta[BB*KD*CH*LL];
__device__ float g_ys[BB*KD*CH*LL];
__device__ float g_yc[BB*CH*LL];
__device__ float g_yln[BB*CH*LL];
__device__ float g_ss[BB*CH*LL];
__device__ float g_p[BB*LL];

__device__ __forceinline__ float softplusf(float x) {
    return (x > 20.f) ? x : log1pf(__expf(x));
}
__device__ __forceinline__ float siluf(float x) {
    return x / (1.f + __expf(-x));
}

// ---------------- generic pixel-contiguous GEMM ----------------
// out[bb][co][pix] (+)= sum_ci W[(wsel)][co][ci] * in[bb*inStride + ci*LL + pix] (+ bias)
// blockDim = 64, each thread: 4 pixels x 8 outputs. grid: (LL/256, ceil(M/8), NB)
__global__ void gemm_pw(const float* __restrict__ in, size_t inStride,
                        const float* __restrict__ W, const float* __restrict__ bias,
                        float* __restrict__ out, size_t outStride,
                        int M, int KK, int perBatchW, int act, int accum)
{
    extern __shared__ float sW[];
    int bb = blockIdx.z;
    int wsel = perBatchW ? (bb & 3) : 0;
    int co0 = blockIdx.y * 8;
    const float* Wp = W + (size_t)wsel * M * KK;
    for (int i = threadIdx.x; i < 8 * KK; i += blockDim.x) {
        int co = co0 + i / KK;
        sW[i] = (co < M) ? Wp[(size_t)co * KK + (i % KK)] : 0.f;
    }
    __syncthreads();
    int pix = blockIdx.x * 256 + threadIdx.x * 4;
    const float* ip = in + (size_t)bb * inStride + pix;
    float4 acc[8];
#pragma unroll
    for (int j = 0; j < 8; j++) {
        float bv = 0.f;
        if (bias != nullptr && (co0 + j) < M) bv = bias[wsel * M + co0 + j];
        acc[j] = make_float4(bv, bv, bv, bv);
    }
#pragma unroll 2
    for (int ci = 0; ci < KK; ci++) {
        float4 v = *reinterpret_cast<const float4*>(ip + (size_t)ci * LL);
#pragma unroll
        for (int j = 0; j < 8; j++) {
            float w = sW[j * KK + ci];
            acc[j].x = fmaf(w, v.x, acc[j].x);
            acc[j].y = fmaf(w, v.y, acc[j].y);
            acc[j].z = fmaf(w, v.z, acc[j].z);
            acc[j].w = fmaf(w, v.w, acc[j].w);
        }
    }
#pragma unroll
    for (int j = 0; j < 8; j++) {
        int co = co0 + j;
        if (co >= M) continue;
        float4 r = acc[j];
        if (act == 1) {
            r.x = softplusf(r.x); r.y = softplusf(r.y);
            r.z = softplusf(r.z); r.w = softplusf(r.w);
        }
        float* op = out + (size_t)bb * outStride + (size_t)co * LL + pix;
        if (accum) {
            float4 o = *reinterpret_cast<const float4*>(op);
            r.x += o.x; r.y += o.y; r.z += o.z; r.w += o.w;
        }
        *reinterpret_cast<float4*>(op) = r;
    }
}

// ---------------- fused 6x depthwise dilated conv + BN ----------------
// dr = sum_i bn_i(dwconv_i(y)); all receptive fields within +-6.
// block (32,8): 32x32 output tile per (b,c); each thread 4 rows (stride 8).
__global__ void dwconv6_kernel(const float* __restrict__ lk_w, const float* __restrict__ lk_bn,
                               const float* __restrict__ b0w, const float* __restrict__ b1w,
                               const float* __restrict__ b2w, const float* __restrict__ b3w,
                               const float* __restrict__ b4w, const float* __restrict__ br_bn)
{
    __shared__ float sIn[44 * 44];
    __shared__ float sWt[270];
    int bc = blockIdx.z;
    int c = bc % CH;
    int h0 = blockIdx.y * 32;
    int w0 = blockIdx.x * 32;
    const float* in = g_y + (size_t)bc * LL;
    int tid = threadIdx.y * 32 + threadIdx.x;

    float s_lk = lk_bn[c] * rsqrtf(lk_bn[3 * CH + c] + 1e-5f);
    float sbr[5];
#pragma unroll
    for (int i = 0; i < 5; i++)
        sbr[i] = br_bn[(i * 4 + 0) * CH + c] * rsqrtf(br_bn[(i * 4 + 3) * CH + c] + 1e-5f);

    for (int i = tid; i < 270; i += 256) {
        float w;
        if (i < 169)      w = lk_w[c * 169 + i] * s_lk;
        else if (i < 194) w = b0w[c * 25 + (i - 169)] * sbr[0];
        else if (i < 243) w = b1w[c * 49 + (i - 194)] * sbr[1];
        else if (i < 252) w = b2w[c * 9 + (i - 243)] * sbr[2];
        else if (i < 261) w = b3w[c * 9 + (i - 252)] * sbr[3];
        else              w = b4w[c * 9 + (i - 261)] * sbr[4];
        sWt[i] = w;
    }
    for (int i = tid; i < 44 * 44; i += 256) {
        int r = i / 44, cl = i % 44;
        int gh = h0 - 6 + r, gw = w0 - 6 + cl;
        float v = 0.f;
        if (gh >= 0 && gh < HH && gw >= 0 && gw < WW) v = in[gh * WW + gw];
        sIn[i] = v;
    }
    __syncthreads();

    int tx = threadIdx.x, ty = threadIdx.y;
    float a0 = 0.f, a1 = 0.f, a2 = 0.f, a3 = 0.f;
    const float* base = sIn + (ty + 6) * 44 + (tx + 6);

    // 13x13 dil 1
#pragma unroll 1
    for (int ky = 0; ky < 13; ky++) {
        const float* rp = base + (ky - 6) * 44;
#pragma unroll
        for (int kx = 0; kx < 13; kx++) {
            float w = sWt[ky * 13 + kx];
            int dx = kx - 6;
            a0 = fmaf(w, rp[dx], a0);
            a1 = fmaf(w, rp[dx + 352], a1);
            a2 = fmaf(w, rp[dx + 704], a2);
            a3 = fmaf(w, rp[dx + 1056], a3);
        }
    }
#define BRANCH(KSZ, DIL, OFF) \
    { const int hk = (KSZ - 1) / 2; \
      _Pragma("unroll 1") \
      for (int ky = 0; ky < KSZ; ky++) { \
          const float* rp = base + (ky - hk) * DIL * 44; \
          _Pragma("unroll") \
          for (int kx = 0; kx < KSZ; kx++) { \
              float w = sWt[OFF + ky * KSZ + kx]; \
              int dx = (kx - hk) * DIL; \
              a0 = fmaf(w, rp[dx], a0); \
              a1 = fmaf(w, rp[dx + 352], a1); \
              a2 = fmaf(w, rp[dx + 704], a2); \
              a3 = fmaf(w, rp[dx + 1056], a3); \
          } } }
    BRANCH(5, 1, 169)
    BRANCH(7, 2, 194)
    BRANCH(3, 3, 243)
    BRANCH(3, 4, 252)
    BRANCH(3, 5, 261)
#undef BRANCH

    float T = lk_bn[CH + c] - lk_bn[2 * CH + c] * s_lk;
#pragma unroll
    for (int i = 0; i < 5; i++)
        T += br_bn[(i * 4 + 1) * CH + c] - br_bn[(i * 4 + 2) * CH + c] * sbr[i];

    float* op = g_dr + (size_t)bc * LL;
    op[(h0 + ty + 0) * WW + w0 + tx]  = a0 + T;
    op[(h0 + ty + 8) * WW + w0 + tx]  = a1 + T;
    op[(h0 + ty + 16) * WW + w0 + tx] = a2 + T;
    op[(h0 + ty + 24) * WW + w0 + tx] = a3 + T;
}

// ---------------- 3x3 depthwise conv + bias + silu on xp ----------------
__global__ void dwconv3_silu_kernel(const float* __restrict__ dw_w, const float* __restrict__ dw_b)
{
    __shared__ float sIn[10 * 66];
    int bc = blockIdx.z;
    int c = bc % CH;
    int b = bc / CH;
    int h0 = blockIdx.y * 8;
    const float* in = g_xz + ((size_t)b * FGC + c) * LL; // xp = first 96 channels
    int tid = threadIdx.y * 64 + threadIdx.x;
    for (int i = tid; i < 10 * 66; i += 512) {
        int r = i / 66, cl = i % 66;
        int gh = h0 - 1 + r, gw = -1 + cl;
        sIn[i] = (gh >= 0 && gh < HH && gw >= 0 && gw < WW) ? in[gh * WW + gw] : 0.f;
    }
    float wreg[9];
#pragma unroll
    for (int i = 0; i < 9; i++) wreg[i] = dw_w[c * 9 + i];
    __syncthreads();
    int tx = threadIdx.x, ty = threadIdx.y;
    float a = dw_b[c];
#pragma unroll
    for (int ky = 0; ky < 3; ky++)
#pragma unroll
        for (int kx = 0; kx < 3; kx++)
            a = fmaf(wreg[ky * 3 + kx], sIn[(ty + ky) * 66 + tx + kx], a);
    g_xc[(size_t)bc * LL + (h0 + ty) * WW + tx] = siluf(a);
}

// ---------------- build 4-direction scan inputs ----------------
__global__ void build_xs_kernel()
{
    int idx = blockIdx.x * blockDim.x + threadIdx.x;
    if (idx >= BB * CH * LL) return;
    int l = idx % LL;
    int bc = idx / LL;
    int b = bc / CH, c = bc % CH;
    float v = g_xc[idx];
    int h = l >> 6, w = l & 63;
    int lt = (w << 6) | h;
    size_t base = ((size_t)b * KD * CH + c) * LL;
    g_xs[base + l] = v;
    g_xs[base + (size_t)CH * LL + lt] = v;
    g_xs[base + (size_t)2 * CH * LL + (LL - 1 - l)] = v;
    g_xs[base + (size_t)3 * CH * LL + (LL - 1 - lt)] = v;
}

// ---------------- repack B/C rows of dbl into [l][n] ----------------
__global__ void repack_kernel()
{
    __shared__ float sB[16][33], sC[16][33];
    int bk = blockIdx.y;
    int l0 = blockIdx.x * 32;
    int tid = threadIdx.x;
    int n = tid >> 5, i = tid & 31;
    const float* dp = g_dbl + (size_t)bk * DBLR * LL;
    sB[n][i] = dp[(size_t)(RKN + n) * LL + l0 + i];
    sC[n][i] = dp[(size_t)(RKN + NST + n) * LL + l0 + i];
    __syncthreads();
    int li = tid >> 4, n2 = tid & 15;
    size_t o = (size_t)bk * LL * NST + (size_t)(l0 + li) * NST + n2;
    g_Bt[o] = sB[n2][li];
    g_Ct[o] = sC[n2][li];
}

// ---------------- selective scan: one 16-lane group per (b,k,c) ----------------
__global__ void scan_kernel(const float* __restrict__ A_log, const float* __restrict__ Ds)
{
    int g = blockIdx.x * (blockDim.x >> 4) + (threadIdx.x >> 4);
    int n = threadIdx.x & 15;
    int b = g / (KD * CH);
    int k = (g / CH) & 3;
    int c = g % CH;
    float A = -__expf(A_log[(size_t)(k * CH + c) * NST + n]);
    float D = Ds[k * CH + c];
    size_t chan = ((size_t)(b * KD + k) * CH + c) * LL;
    const float* __restrict__ dp = g_delta + chan;
    const float* __restrict__ up = g_xs + chan;
    const float* __restrict__ Bp = g_Bt + (size_t)(b * KD + k) * LL * NST + n;
    const float* __restrict__ Cp = g_Ct + (size_t)(b * KD + k) * LL * NST + n;
    float* __restrict__ yp = g_ys + chan;
    float h = 0.f;
#pragma unroll 2
    for (int l = 0; l < LL; l++) {
        float dl = dp[l];
        float uu = up[l];
        float Bv = Bp[(size_t)l * NST];
        float Cv = Cp[(size_t)l * NST];
        float e = __expf(dl * A);
        h = fmaf(e, h, dl * uu * Bv);
        float t = h * Cv;
#pragma unroll
        for (int off = 1; off < 16; off <<= 1)
            t += __shfl_xor_sync(0xffffffffu, t, off);
        if (n == 0) yp[l] = t + D * uu;
    }
}

// ---------------- combine 4 directions back to hw order ----------------
__global__ void combine_kernel()
{
    int idx = blockIdx.x * blockDim.x + threadIdx.x;
    if (idx >= BB * CH * LL) return;
    int l = idx % LL;
    int bc = idx / LL;
    int b = bc / CH, c = bc % CH;
    int h = l >> 6, w = l & 63;
    int lt = (w << 6) | h;
    size_t base = ((size_t)b * KD * CH + c) * LL;
    float v = g_ys[base + l]
            + g_ys[base + (size_t)CH * LL + lt]
            + g_ys[base + (size_t)2 * CH * LL + (LL - 1 - l)]
            + g_ys[base + (size_t)3 * CH * LL + (LL - 1 - lt)];
    g_yc[idx] = v;
}

// ---------------- LayerNorm over channel + silu(z) gate ----------------
__global__ void ln_gate_kernel(const float* __restrict__ ln_g, const float* __restrict__ ln_b)
{
    __shared__ float sY[CH * 33];
    __shared__ float sZ[CH * 33];
    int b = blockIdx.y;
    int l0 = blockIdx.x * 32;
    int tid = threadIdx.x;
    const float* yp = g_yc + (size_t)b * CH * LL;
    const float* zp = g_xz + ((size_t)b * FGC + CH) * LL;
    for (int i = tid; i < CH * 32; i += 256) {
        int cc = i >> 5, ii = i & 31;
        sY[cc * 33 + ii] = yp[(size_t)cc * LL + l0 + ii];
        sZ[cc * 33 + ii] = zp[(size_t)cc * LL + l0 + ii];
    }
    __syncthreads();
    int warp = tid >> 5, lane = tid & 31;
    float g0 = ln_g[lane], g1 = ln_g[lane + 32], g2 = ln_g[lane + 64];
    float bb0 = ln_b[lane], bb1 = ln_b[lane + 32], bb2 = ln_b[lane + 64];
    for (int q = 0; q < 4; q++) {
        int i = warp * 4 + q;
        float y0 = sY[lane * 33 + i], y1 = sY[(lane + 32) * 33 + i], y2 = sY[(lane + 64) * 33 + i];
        float s = y0 + y1 + y2;
        float ss = y0 * y0 + y1 * y1 + y2 * y2;
#pragma unroll
        for (int off = 16; off; off >>= 1) {
            s += __shfl_xor_sync(0xffffffffu, s, off);
            ss += __shfl_xor_sync(0xffffffffu, ss, off);
        }
        float mean = s * (1.f / 96.f);
        float var = ss * (1.f / 96.f) - mean * mean;
        float rs = rsqrtf(var + 1e-5f);
        float z0 = sZ[lane * 33 + i], z1 = sZ[(lane + 32) * 33 + i], z2 = sZ[(lane + 64) * 33 + i];
        float r0 = ((y0 - mean) * rs * g0 + bb0) * siluf(z0);
        float r1 = ((y1 - mean) * rs * g1 + bb1) * siluf(z1);
        float r2 = ((y2 - mean) * rs * g2 + bb2) * siluf(z2);
        sY[lane * 33 + i] = r0;
        sY[(lane + 32) * 33 + i] = r1;
        sY[(lane + 64) * 33 + i] = r2;
    }
    __syncthreads();
    float* op = g_yln + (size_t)b * CH * LL;
    for (int i = tid; i < CH * 32; i += 256) {
        int cc = i >> 5, ii = i & 31;
        op[(size_t)cc * LL + l0 + ii] = sY[cc * 33 + ii];
    }
}

// ---------------- psi gate: sigmoid(bn(conv1x1(relu(y)))) ----------------
__global__ void psi_kernel(const float* __restrict__ psi_w, const float* __restrict__ psi_b,
                           const float* __restrict__ psi_bn)
{
    int idx = blockIdx.x * blockDim.x + threadIdx.x;
    if (idx >= BB * LL) return;
    int b = idx / LL, l = idx % LL;
    const float* yp = g_y + (size_t)b * CH * LL + l;
    float acc = psi_b[0];
#pragma unroll 4
    for (int cc = 0; cc < CH; cc++)
        acc = fmaf(psi_w[cc], fmaxf(yp[(size_t)cc * LL], 0.f), acc);
    float s = psi_bn[0] * rsqrtf(psi_bn[3] + 1e-5f);
    float v = (acc - psi_bn[2]) * s + psi_bn[1];
    g_p[idx] = 1.f / (1.f + __expf(-v));
}

// ---------------- final: out = p*x + relu(ss) ----------------
__global__ void final_kernel(const float* __restrict__ x, float* __restrict__ out)
{
    int i4 = blockIdx.x * blockDim.x + threadIdx.x;
    if (i4 >= BB * CH * LL / 4) return;
    int idx = i4 * 4;
    int b = idx / (CH * LL);
    int l = idx % LL;
    float4 xv = *reinterpret_cast<const float4*>(x + idx);
    float4 sv = *reinterpret_cast<const float4*>(g_ss + idx);
    float4 pv = *reinterpret_cast<const float4*>(g_p + (size_t)b * LL + l);
    float4 o;
    o.x = pv.x * xv.x + fmaxf(sv.x, 0.f);
    o.y = pv.y * xv.y + fmaxf(sv.y, 0.f);
    o.z = pv.z * xv.z + fmaxf(sv.z, 0.f);
    o.w = pv.w * xv.w + fmaxf(sv.w, 0.f);
    *reinterpret_cast<float4*>(out + idx) = o;
}

// ---------------- host launch ----------------
extern "C" void kernel_launch(void* const* d_in, const int* in_sizes, int n_in,
                              void* d_out, int out_size)
{
    const float* g        = (const float*)d_in[0];
    const float* x        = (const float*)d_in[1];
    const float* wg_w     = (const float*)d_in[2];
    const float* wg_b     = (const float*)d_in[3];
    const float* wx_w     = (const float*)d_in[4];
    const float* wx_b     = (const float*)d_in[5];
    const float* psi_w    = (const float*)d_in[6];
    const float* psi_b    = (const float*)d_in[7];
    const float* psi_bn   = (const float*)d_in[8];
    const float* lk_w     = (const float*)d_in[9];
    const float* lk_bn    = (const float*)d_in[10];
    const float* br0      = (const float*)d_in[11];
    const float* br1      = (const float*)d_in[12];
    const float* br2      = (const float*)d_in[13];
    const float* br3      = (const float*)d_in[14];
    const float* br4      = (const float*)d_in[15];
    const float* br_bn    = (const float*)d_in[16];
    const float* in_proj_w= (const float*)d_in[17];
    const float* dw_w     = (const float*)d_in[18];
    const float* dw_b     = (const float*)d_in[19];
    const float* xproj_w  = (const float*)d_in[20];
    const float* dtproj_w = (const float*)d_in[21];
    const float* dtproj_b = (const float*)d_in[22];
    const float* A_log    = (const float*)d_in[23];
    const float* Ds       = (const float*)d_in[24];
    const float* ln_g     = (const float*)d_in[25];
    const float* ln_b     = (const float*)d_in[26];
    const float* outp_w   = (const float*)d_in[27];

    float *py, *pdr, *pxz, *pxs, *pdbl, *pdelta, *pyln, *pss;
    cudaGetSymbolAddress((void**)&py, g_y);
    cudaGetSymbolAddress((void**)&pdr, g_dr);
    cudaGetSymbolAddress((void**)&pxz, g_xz);
    cudaGetSymbolAddress((void**)&pxs, g_xs);
    cudaGetSymbolAddress((void**)&pdbl, g_dbl);
    cudaGetSymbolAddress((void**)&pdelta, g_delta);
    cudaGetSymbolAddress((void**)&pyln, g_yln);
    cudaGetSymbolAddress((void**)&pss, g_ss);

    // 1-2: y = conv1x1(g) + conv1x1(x)
    gemm_pw<<<dim3(16, 12, BB), 64, 8 * 192 * 4>>>(g, (size_t)FGC * LL, wg_w, wg_b,
                                                   py, (size_t)CH * LL, CH, FGC, 0, 0, 0);
    gemm_pw<<<dim3(16, 12, BB), 64, 8 * 96 * 4>>>(x, (size_t)CH * LL, wx_w, wx_b,
                                                  py, (size_t)CH * LL, CH, CH, 0, 0, 1);
    // 3: fused 6 depthwise convs + BN -> dr
    dwconv6_kernel<<<dim3(2, 2, BB * CH), dim3(32, 8)>>>(lk_w, lk_bn, br0, br1, br2, br3, br4, br_bn);
    // 4: in_proj -> xz
    gemm_pw<<<dim3(16, 24, BB), 64, 8 * 96 * 4>>>(pdr, (size_t)CH * LL, in_proj_w, nullptr,
                                                  pxz, (size_t)FGC * LL, FGC, CH, 0, 0, 0);
    // 5: depthwise 3x3 + silu -> xc
    dwconv3_silu_kernel<<<dim3(1, 8, BB * CH), dim3(64, 8)>>>(dw_w, dw_b);
    // 6: build 4-direction xs
    build_xs_kernel<<<(BB * CH * LL + 255) / 256, 256>>>();
    // 7: xproj -> dbl  (batches = b*4+k, per-direction weights)
    gemm_pw<<<dim3(16, 5, BB * KD), 64, 8 * 96 * 4>>>(pxs, (size_t)CH * LL, xproj_w, nullptr,
                                                      pdbl, (size_t)DBLR * LL, DBLR, CH, 1, 0, 0);
    // 8: repack B/C into [l][n]
    repack_kernel<<<dim3(LL / 32, BB * KD), 512>>>();
    // 9: dtproj + softplus -> delta
    gemm_pw<<<dim3(16, 12, BB * KD), 64, 8 * 6 * 4>>>(pdbl, (size_t)DBLR * LL, dtproj_w, dtproj_b,
                                                      pdelta, (size_t)CH * LL, CH, RKN, 1, 1, 0);
    // 10: selective scan
    scan_kernel<<<BB * KD * CH * NST / 128, 128>>>(A_log, Ds);
    // 11: combine directions
    combine_kernel<<<(BB * CH * LL + 255) / 256, 256>>>();
    // 12: LN + silu gate
    ln_gate_kernel<<<dim3(LL / 32, BB), 256>>>(ln_g, ln_b);
    // 13: out_proj -> ss
    gemm_pw<<<dim3(16, 12, BB), 64, 8 * 96 * 4>>>(pyln, (size_t)CH * LL, outp_w, nullptr,
                                                  pss, (size_t)CH * LL, CH, CH, 0, 0, 0);
    // 14: psi gate
    psi_kernel<<<(BB * LL + 255) / 256, 256>>>(psi_w, psi_b, psi_bn);
    // 15: final
    final_kernel<<<(BB * CH * LL / 4 + 255) / 256, 256>>>(x, (float*)d_out);
}

// round 5
// speedup vs baseline: 3.8604x; 3.8604x over previous
#include <cuda_runtime.h>
#include <math.h>

#define BB 2
#define CH 96
#define FGC 192
#define HH 64
#define WW 64
#define LL 4096
#define NST 16
#define RKN 6
#define KD 4
#define DBLR 38
#define CHUNK 256
#define NCHUNK 16

// ---------------- scratch (static device globals; no allocations) ----------------
__device__ float g_y[BB*CH*LL];
__device__ float g_dr[BB*CH*LL];
__device__ float g_xz[BB*2*CH*LL];
__device__ float g_xc[BB*CH*LL];
__device__ float g_xs[BB*KD*CH*LL];
__device__ float g_dbl[BB*KD*DBLR*LL];
__device__ float g_Bt[BB*KD*LL*NST];
__device__ float g_Ct[BB*KD*LL*NST];
__device__ float g_delta[BB*KD*CH*LL];
__device__ float g_ys[BB*KD*CH*LL];
__device__ float g_yc[BB*CH*LL];
__device__ float g_yln[BB*CH*LL];
__device__ float g_ss[BB*CH*LL];
__device__ float g_p[BB*LL];

__device__ __forceinline__ float softplusf(float x) {
    return (x > 20.f) ? x : log1pf(__expf(x));
}
__device__ __forceinline__ float siluf(float x) {
    return x / (1.f + __expf(-x));
}

// ---------------- generic pixel-contiguous GEMM ----------------
// thread: 4 pixels x 4 outputs. blockDim=64. grid: (LL/256, ceil(M/4), NB)
__global__ void gemm_pw(const float* __restrict__ in, size_t inStride,
                        const float* __restrict__ W, const float* __restrict__ bias,
                        float* __restrict__ out, size_t outStride,
                        int M, int KK, int perBatchW, int act, int accum)
{
    extern __shared__ float sW[];
    int bb = blockIdx.z;
    int wsel = perBatchW ? (bb & 3) : 0;
    int co0 = blockIdx.y * 4;
    const float* Wp = W + (size_t)wsel * M * KK;
    for (int i = threadIdx.x; i < 4 * KK; i += blockDim.x) {
        int co = co0 + i / KK;
        sW[i] = (co < M) ? Wp[(size_t)co * KK + (i % KK)] : 0.f;
    }
    __syncthreads();
    int pix = blockIdx.x * 256 + threadIdx.x * 4;
    const float* ip = in + (size_t)bb * inStride + pix;
    float4 acc[4];
#pragma unroll
    for (int j = 0; j < 4; j++) {
        float bv = 0.f;
        if (bias != nullptr && (co0 + j) < M) bv = bias[wsel * M + co0 + j];
        acc[j] = make_float4(bv, bv, bv, bv);
    }
#pragma unroll 4
    for (int ci = 0; ci < KK; ci++) {
        float4 v = *reinterpret_cast<const float4*>(ip + (size_t)ci * LL);
#pragma unroll
        for (int j = 0; j < 4; j++) {
            float w = sW[j * KK + ci];
            acc[j].x = fmaf(w, v.x, acc[j].x);
            acc[j].y = fmaf(w, v.y, acc[j].y);
            acc[j].z = fmaf(w, v.z, acc[j].z);
            acc[j].w = fmaf(w, v.w, acc[j].w);
        }
    }
#pragma unroll
    for (int j = 0; j < 4; j++) {
        int co = co0 + j;
        if (co >= M) continue;
        float4 r = acc[j];
        if (act == 1) {
            r.x = softplusf(r.x); r.y = softplusf(r.y);
            r.z = softplusf(r.z); r.w = softplusf(r.w);
        }
        float* op = out + (size_t)bb * outStride + (size_t)co * LL + pix;
        if (accum) {
            float4 o = *reinterpret_cast<const float4*>(op);
            r.x += o.x; r.y += o.y; r.z += o.z; r.w += o.w;
        }
        *reinterpret_cast<float4*>(op) = r;
    }
}

// ---------------- fused 6x depthwise dilated conv + BN ----------------
__global__ void dwconv6_kernel(const float* __restrict__ lk_w, const float* __restrict__ lk_bn,
                               const float* __restrict__ b0w, const float* __restrict__ b1w,
                               const float* __restrict__ b2w, const float* __restrict__ b3w,
                               const float* __restrict__ b4w, const float* __restrict__ br_bn)
{
    __shared__ float sIn[44 * 44];
    __shared__ float sWt[270];
    int bc = blockIdx.z;
    int c = bc % CH;
    int h0 = blockIdx.y * 32;
    int w0 = blockIdx.x * 32;
    const float* in = g_y + (size_t)bc * LL;
    int tid = threadIdx.y * 32 + threadIdx.x;

    float s_lk = lk_bn[c] * rsqrtf(lk_bn[3 * CH + c] + 1e-5f);
    float sbr[5];
#pragma unroll
    for (int i = 0; i < 5; i++)
        sbr[i] = br_bn[(i * 4 + 0) * CH + c] * rsqrtf(br_bn[(i * 4 + 3) * CH + c] + 1e-5f);

    for (int i = tid; i < 270; i += 256) {
        float w;
        if (i < 169)      w = lk_w[c * 169 + i] * s_lk;
        else if (i < 194) w = b0w[c * 25 + (i - 169)] * sbr[0];
        else if (i < 243) w = b1w[c * 49 + (i - 194)] * sbr[1];
        else if (i < 252) w = b2w[c * 9 + (i - 243)] * sbr[2];
        else if (i < 261) w = b3w[c * 9 + (i - 252)] * sbr[3];
        else              w = b4w[c * 9 + (i - 261)] * sbr[4];
        sWt[i] = w;
    }
    for (int i = tid; i < 44 * 44; i += 256) {
        int r = i / 44, cl = i % 44;
        int gh = h0 - 6 + r, gw = w0 - 6 + cl;
        float v = 0.f;
        if (gh >= 0 && gh < HH && gw >= 0 && gw < WW) v = in[gh * WW + gw];
        sIn[i] = v;
    }
    __syncthreads();

    int tx = threadIdx.x, ty = threadIdx.y;
    float a0 = 0.f, a1 = 0.f, a2 = 0.f, a3 = 0.f;
    const float* base = sIn + (ty + 6) * 44 + (tx + 6);

#pragma unroll 1
    for (int ky = 0; ky < 13; ky++) {
        const float* rp = base + (ky - 6) * 44;
#pragma unroll
        for (int kx = 0; kx < 13; kx++) {
            float w = sWt[ky * 13 + kx];
            int dx = kx - 6;
            a0 = fmaf(w, rp[dx], a0);
            a1 = fmaf(w, rp[dx + 352], a1);
            a2 = fmaf(w, rp[dx + 704], a2);
            a3 = fmaf(w, rp[dx + 1056], a3);
        }
    }
#define BRANCH(KSZ, DIL, OFF) \
    { const int hk = (KSZ - 1) / 2; \
      _Pragma("unroll 1") \
      for (int ky = 0; ky < KSZ; ky++) { \
          const float* rp = base + (ky - hk) * DIL * 44; \
          _Pragma("unroll") \
          for (int kx = 0; kx < KSZ; kx++) { \
              float w = sWt[OFF + ky * KSZ + kx]; \
              int dx = (kx - hk) * DIL; \
              a0 = fmaf(w, rp[dx], a0); \
              a1 = fmaf(w, rp[dx + 352], a1); \
              a2 = fmaf(w, rp[dx + 704], a2); \
              a3 = fmaf(w, rp[dx + 1056], a3); \
          } } }
    BRANCH(5, 1, 169)
    BRANCH(7, 2, 194)
    BRANCH(3, 3, 243)
    BRANCH(3, 4, 252)
    BRANCH(3, 5, 261)
#undef BRANCH

    float T = lk_bn[CH + c] - lk_bn[2 * CH + c] * s_lk;
#pragma unroll
    for (int i = 0; i < 5; i++)
        T += br_bn[(i * 4 + 1) * CH + c] - br_bn[(i * 4 + 2) * CH + c] * sbr[i];

    float* op = g_dr + (size_t)bc * LL;
    op[(h0 + ty + 0) * WW + w0 + tx]  = a0 + T;
    op[(h0 + ty + 8) * WW + w0 + tx]  = a1 + T;
    op[(h0 + ty + 16) * WW + w0 + tx] = a2 + T;
    op[(h0 + ty + 24) * WW + w0 + tx] = a3 + T;
}

// ---------------- 3x3 depthwise conv + bias + silu on xp ----------------
__global__ void dwconv3_silu_kernel(const float* __restrict__ dw_w, const float* __restrict__ dw_b)
{
    __shared__ float sIn[10 * 66];
    int bc = blockIdx.z;
    int c = bc % CH;
    int b = bc / CH;
    int h0 = blockIdx.y * 8;
    const float* in = g_xz + ((size_t)b * FGC + c) * LL;
    int tid = threadIdx.y * 64 + threadIdx.x;
    for (int i = tid; i < 10 * 66; i += 512) {
        int r = i / 66, cl = i % 66;
        int gh = h0 - 1 + r, gw = -1 + cl;
        sIn[i] = (gh >= 0 && gh < HH && gw >= 0 && gw < WW) ? in[gh * WW + gw] : 0.f;
    }
    float wreg[9];
#pragma unroll
    for (int i = 0; i < 9; i++) wreg[i] = dw_w[c * 9 + i];
    __syncthreads();
    int tx = threadIdx.x, ty = threadIdx.y;
    float a = dw_b[c];
#pragma unroll
    for (int ky = 0; ky < 3; ky++)
#pragma unroll
        for (int kx = 0; kx < 3; kx++)
            a = fmaf(wreg[ky * 3 + kx], sIn[(ty + ky) * 66 + tx + kx], a);
    g_xc[(size_t)bc * LL + (h0 + ty) * WW + tx] = siluf(a);
}

// ---------------- build 4-direction scan inputs ----------------
__global__ void build_xs_kernel()
{
    int idx = blockIdx.x * blockDim.x + threadIdx.x;
    if (idx >= BB * CH * LL) return;
    int l = idx % LL;
    int bc = idx / LL;
    int b = bc / CH, c = bc % CH;
    float v = g_xc[idx];
    int h = l >> 6, w = l & 63;
    int lt = (w << 6) | h;
    size_t base = ((size_t)b * KD * CH + c) * LL;
    g_xs[base + l] = v;
    g_xs[base + (size_t)CH * LL + lt] = v;
    g_xs[base + (size_t)2 * CH * LL + (LL - 1 - l)] = v;
    g_xs[base + (size_t)3 * CH * LL + (LL - 1 - lt)] = v;
}

// ---------------- repack B/C rows of dbl into [l][n] ----------------
__global__ void repack_kernel()
{
    __shared__ float sB[16][33], sC[16][33];
    int bk = blockIdx.y;
    int l0 = blockIdx.x * 32;
    int tid = threadIdx.x;
    int n = tid >> 5, i = tid & 31;
    const float* dp = g_dbl + (size_t)bk * DBLR * LL;
    sB[n][i] = dp[(size_t)(RKN + n) * LL + l0 + i];
    sC[n][i] = dp[(size_t)(RKN + NST + n) * LL + l0 + i];
    __syncthreads();
    int li = tid >> 4, n2 = tid & 15;
    size_t o = (size_t)bk * LL * NST + (size_t)(l0 + li) * NST + n2;
    g_Bt[o] = sB[n2][li];
    g_Ct[o] = sC[n2][li];
}

// ---------------- chunked-parallel selective scan ----------------
// block = one (b,k,c) chain, 256 threads: thread = (chunk g in [0,16), state n in [0,16))
// Pass1: per-chunk composed transform (E,F). Chunk prefix via smem (serial 16).
// Pass2: replay chunk from h0, shfl-reduce y over states.
__global__ void scan_kernel(const float* __restrict__ A_log, const float* __restrict__ Ds)
{
    __shared__ float sE[NCHUNK][NST + 1];
    __shared__ float sF[NCHUNK][NST + 1];
    int blk = blockIdx.x;                    // ((b*KD)+k)*CH + c
    int c = blk % CH;
    int bk = blk / CH;                       // b*KD + k
    int k = bk & 3;
    int t = threadIdx.x;
    int g = t >> 4, n = t & 15;

    float A = -__expf(A_log[(size_t)(k * CH + c) * NST + n]);
    float D = Ds[k * CH + c];
    size_t chan = (size_t)blk * LL;
    const float* __restrict__ dp = g_delta + chan;
    const float* __restrict__ up = g_xs + chan;
    const float* __restrict__ Bp = g_Bt + (size_t)bk * LL * NST;
    const float* __restrict__ Cp = g_Ct + (size_t)bk * LL * NST;
    float* __restrict__ yp = g_ys + chan;

    int l0 = g * CHUNK;
    // ---- pass 1: chunk transform with h0 = 0 ----
    float E = 1.f, F = 0.f;
#pragma unroll 4
    for (int i = 0; i < CHUNK; i++) {
        int l = l0 + i;
        float dl = dp[l];
        float uu = up[l];
        float Bv = Bp[(size_t)l * NST + n];
        float e = __expf(dl * A);
        F = fmaf(e, F, dl * uu * Bv);
        E *= e;
    }
    sE[g][n] = E;
    sF[g][n] = F;
    __syncthreads();
    // ---- chunk prefix: h0 for chunk g ----
    float h = 0.f;
    for (int j = 0; j < g; j++)
        h = fmaf(sE[j][n], h, sF[j][n]);
    // ---- pass 2: replay + output ----
#pragma unroll 4
    for (int i = 0; i < CHUNK; i++) {
        int l = l0 + i;
        float dl = dp[l];
        float uu = up[l];
        float Bv = Bp[(size_t)l * NST + n];
        float Cv = Cp[(size_t)l * NST + n];
        float e = __expf(dl * A);
        h = fmaf(e, h, dl * uu * Bv);
        float tt = h * Cv;
#pragma unroll
        for (int off = 1; off < 16; off <<= 1)
            tt += __shfl_xor_sync(0xffffffffu, tt, off);
        if (n == 0) yp[l] = tt + D * uu;
    }
}

// ---------------- combine 4 directions back to hw order ----------------
__global__ void combine_kernel()
{
    int idx = blockIdx.x * blockDim.x + threadIdx.x;
    if (idx >= BB * CH * LL) return;
    int l = idx % LL;
    int bc = idx / LL;
    int b = bc / CH, c = bc % CH;
    int h = l >> 6, w = l & 63;
    int lt = (w << 6) | h;
    size_t base = ((size_t)b * KD * CH + c) * LL;
    float v = g_ys[base + l]
            + g_ys[base + (size_t)CH * LL + lt]
            + g_ys[base + (size_t)2 * CH * LL + (LL - 1 - l)]
            + g_ys[base + (size_t)3 * CH * LL + (LL - 1 - lt)];
    g_yc[idx] = v;
}

// ---------------- LayerNorm over channel + silu(z) gate ----------------
__global__ void ln_gate_kernel(const float* __restrict__ ln_g, const float* __restrict__ ln_b)
{
    __shared__ float sY[CH * 33];
    __shared__ float sZ[CH * 33];
    int b = blockIdx.y;
    int l0 = blockIdx.x * 32;
    int tid = threadIdx.x;
    const float* yp = g_yc + (size_t)b * CH * LL;
    const float* zp = g_xz + ((size_t)b * FGC + CH) * LL;
    for (int i = tid; i < CH * 32; i += 256) {
        int cc = i >> 5, ii = i & 31;
        sY[cc * 33 + ii] = yp[(size_t)cc * LL + l0 + ii];
        sZ[cc * 33 + ii] = zp[(size_t)cc * LL + l0 + ii];
    }
    __syncthreads();
    int warp = tid >> 5, lane = tid & 31;
    float g0 = ln_g[lane], g1 = ln_g[lane + 32], g2 = ln_g[lane + 64];
    float bb0 = ln_b[lane], bb1 = ln_b[lane + 32], bb2 = ln_b[lane + 64];
    for (int q = 0; q < 4; q++) {
        int i = warp * 4 + q;
        float y0 = sY[lane * 33 + i], y1 = sY[(lane + 32) * 33 + i], y2 = sY[(lane + 64) * 33 + i];
        float s = y0 + y1 + y2;
        float ss = y0 * y0 + y1 * y1 + y2 * y2;
#pragma unroll
        for (int off = 16; off; off >>= 1) {
            s += __shfl_xor_sync(0xffffffffu, s, off);
            ss += __shfl_xor_sync(0xffffffffu, ss, off);
        }
        float mean = s * (1.f / 96.f);
        float var = ss * (1.f / 96.f) - mean * mean;
        float rs = rsqrtf(var + 1e-5f);
        float z0 = sZ[lane * 33 + i], z1 = sZ[(lane + 32) * 33 + i], z2 = sZ[(lane + 64) * 33 + i];
        float r0 = ((y0 - mean) * rs * g0 + bb0) * siluf(z0);
        float r1 = ((y1 - mean) * rs * g1 + bb1) * siluf(z1);
        float r2 = ((y2 - mean) * rs * g2 + bb2) * siluf(z2);
        sY[lane * 33 + i] = r0;
        sY[(lane + 32) * 33 + i] = r1;
        sY[(lane + 64) * 33 + i] = r2;
    }
    __syncthreads();
    float* op = g_yln + (size_t)b * CH * LL;
    for (int i = tid; i < CH * 32; i += 256) {
        int cc = i >> 5, ii = i & 31;
        op[(size_t)cc * LL + l0 + ii] = sY[cc * 33 + ii];
    }
}

// ---------------- psi gate: sigmoid(bn(conv1x1(relu(y)))) ----------------
__global__ void psi_kernel(const float* __restrict__ psi_w, const float* __restrict__ psi_b,
                           const float* __restrict__ psi_bn)
{
    int idx = blockIdx.x * blockDim.x + threadIdx.x;
    if (idx >= BB * LL) return;
    int b = idx / LL, l = idx % LL;
    const float* yp = g_y + (size_t)b * CH * LL + l;
    float acc = psi_b[0];
#pragma unroll 4
    for (int cc = 0; cc < CH; cc++)
        acc = fmaf(psi_w[cc], fmaxf(yp[(size_t)cc * LL], 0.f), acc);
    float s = psi_bn[0] * rsqrtf(psi_bn[3] + 1e-5f);
    float v = (acc - psi_bn[2]) * s + psi_bn[1];
    g_p[idx] = 1.f / (1.f + __expf(-v));
}

// ---------------- final: out = p*x + relu(ss) ----------------
__global__ void final_kernel(const float* __restrict__ x, float* __restrict__ out)
{
    int i4 = blockIdx.x * blockDim.x + threadIdx.x;
    if (i4 >= BB * CH * LL / 4) return;
    int idx = i4 * 4;
    int b = idx / (CH * LL);
    int l = idx % LL;
    float4 xv = *reinterpret_cast<const float4*>(x + idx);
    float4 sv = *reinterpret_cast<const float4*>(g_ss + idx);
    float4 pv = *reinterpret_cast<const float4*>(g_p + (size_t)b * LL + l);
    float4 o;
    o.x = pv.x * xv.x + fmaxf(sv.x, 0.f);
    o.y = pv.y * xv.y + fmaxf(sv.y, 0.f);
    o.z = pv.z * xv.z + fmaxf(sv.z, 0.f);
    o.w = pv.w * xv.w + fmaxf(sv.w, 0.f);
    *reinterpret_cast<float4*>(out + idx) = o;
}

// ---------------- host launch ----------------
extern "C" void kernel_launch(void* const* d_in, const int* in_sizes, int n_in,
                              void* d_out, int out_size)
{
    const float* g        = (const float*)d_in[0];
    const float* x        = (const float*)d_in[1];
    const float* wg_w     = (const float*)d_in[2];
    const float* wg_b     = (const float*)d_in[3];
    const float* wx_w     = (const float*)d_in[4];
    const float* wx_b     = (const float*)d_in[5];
    const float* psi_w    = (const float*)d_in[6];
    const float* psi_b    = (const float*)d_in[7];
    const float* psi_bn   = (const float*)d_in[8];
    const float* lk_w     = (const float*)d_in[9];
    const float* lk_bn    = (const float*)d_in[10];
    const float* br0      = (const float*)d_in[11];
    const float* br1      = (const float*)d_in[12];
    const float* br2      = (const float*)d_in[13];
    const float* br3      = (const float*)d_in[14];
    const float* br4      = (const float*)d_in[15];
    const float* br_bn    = (const float*)d_in[16];
    const float* in_proj_w= (const float*)d_in[17];
    const float* dw_w     = (const float*)d_in[18];
    const float* dw_b     = (const float*)d_in[19];
    const float* xproj_w  = (const float*)d_in[20];
    const float* dtproj_w = (const float*)d_in[21];
    const float* dtproj_b = (const float*)d_in[22];
    const float* A_log    = (const float*)d_in[23];
    const float* Ds       = (const float*)d_in[24];
    const float* ln_g     = (const float*)d_in[25];
    const float* ln_b     = (const float*)d_in[26];
    const float* outp_w   = (const float*)d_in[27];

    float *py, *pdr, *pxz, *pxs, *pdbl, *pdelta, *pyln, *pss;
    cudaGetSymbolAddress((void**)&py, g_y);
    cudaGetSymbolAddress((void**)&pdr, g_dr);
    cudaGetSymbolAddress((void**)&pxz, g_xz);
    cudaGetSymbolAddress((void**)&pxs, g_xs);
    cudaGetSymbolAddress((void**)&pdbl, g_dbl);
    cudaGetSymbolAddress((void**)&pdelta, g_delta);
    cudaGetSymbolAddress((void**)&pyln, g_yln);
    cudaGetSymbolAddress((void**)&pss, g_ss);

    // 1-2: y = conv1x1(g) + conv1x1(x)
    gemm_pw<<<dim3(16, 24, BB), 64, 4 * 192 * 4>>>(g, (size_t)FGC * LL, wg_w, wg_b,
                                                   py, (size_t)CH * LL, CH, FGC, 0, 0, 0);
    gemm_pw<<<dim3(16, 24, BB), 64, 4 * 96 * 4>>>(x, (size_t)CH * LL, wx_w, wx_b,
                                                  py, (size_t)CH * LL, CH, CH, 0, 0, 1);
    // 3: fused 6 depthwise convs + BN -> dr
    dwconv6_kernel<<<dim3(2, 2, BB * CH), dim3(32, 8)>>>(lk_w, lk_bn, br0, br1, br2, br3, br4, br_bn);
    // 4: in_proj -> xz
    gemm_pw<<<dim3(16, 48, BB), 64, 4 * 96 * 4>>>(pdr, (size_t)CH * LL, in_proj_w, nullptr,
                                                  pxz, (size_t)FGC * LL, FGC, CH, 0, 0, 0);
    // 5: depthwise 3x3 + silu -> xc
    dwconv3_silu_kernel<<<dim3(1, 8, BB * CH), dim3(64, 8)>>>(dw_w, dw_b);
    // 6: build 4-direction xs
    build_xs_kernel<<<(BB * CH * LL + 255) / 256, 256>>>();
    // 7: xproj -> dbl
    gemm_pw<<<dim3(16, 10, BB * KD), 64, 4 * 96 * 4>>>(pxs, (size_t)CH * LL, xproj_w, nullptr,
                                                       pdbl, (size_t)DBLR * LL, DBLR, CH, 1, 0, 0);
    // 8: repack B/C into [l][n]
    repack_kernel<<<dim3(LL / 32, BB * KD), 512>>>();
    // 9: dtproj + softplus -> delta
    gemm_pw<<<dim3(16, 24, BB * KD), 64, 4 * 6 * 4>>>(pdbl, (size_t)DBLR * LL, dtproj_w, dtproj_b,
                                                      pdelta, (size_t)CH * LL, CH, RKN, 1, 1, 0);
    // 10: chunked-parallel selective scan
    scan_kernel<<<BB * KD * CH, 256>>>(A_log, Ds);
    // 11: combine directions
    combine_kernel<<<(BB * CH * LL + 255) / 256, 256>>>();
    // 12: LN + silu gate
    ln_gate_kernel<<<dim3(LL / 32, BB), 256>>>(ln_g, ln_b);
    // 13: out_proj -> ss
    gemm_pw<<<dim3(16, 24, BB), 64, 4 * 96 * 4>>>(pyln, (size_t)CH * LL, outp_w, nullptr,
                                                  pss, (size_t)CH * LL, CH, CH, 0, 0, 0);
    // 14: psi gate
    psi_kernel<<<(BB * LL + 255) / 256, 256>>>(psi_w, psi_b, psi_bn);
    // 15: final
    final_kernel<<<(BB * CH * LL / 4 + 255) / 256, 256>>>(x, (float*)d_out);
}

// round 6
// speedup vs baseline: 3.9258x; 1.0169x over previous
#include <cuda_runtime.h>
#include <math.h>

#define BB 2
#define CH 96
#define FGC 192
#define HH 64
#define WW 64
#define LL 4096
#define NST 16
#define RKN 6
#define KD 4
#define DBLR 38
#define CHUNK 256
#define NCHUNK 16

// ---------------- scratch (static device globals; no allocations) ----------------
__device__ float g_y[BB*CH*LL];
__device__ float g_dr[BB*CH*LL];
__device__ float g_xz[BB*2*CH*LL];
__device__ float g_xc[BB*CH*LL];
__device__ float g_dbl[BB*KD*DBLR*LL];
__device__ float g_Bt[BB*KD*LL*NST];
__device__ float g_Ct[BB*KD*LL*NST];
__device__ float g_delta[BB*KD*CH*LL];
__device__ float g_ys[BB*KD*CH*LL];
__device__ float g_EF[BB*KD*CH*NCHUNK*2*NST];
__device__ float g_yln[BB*CH*LL];
__device__ float g_ss[BB*CH*LL];
__device__ float g_p[BB*LL];

__device__ __forceinline__ float softplusf(float x) {
    return (x > 20.f) ? x : log1pf(__expf(x));
}
__device__ __forceinline__ float siluf(float x) {
    return x / (1.f + __expf(-x));
}
// scan-order l -> hw-order index for direction k
__device__ __forceinline__ int mapk(int k, int l) {
    int l2 = (k & 2) ? (4095 - l) : l;
    return (k & 1) ? (((l2 & 63) << 6) | (l2 >> 6)) : l2;
}

// ---------------- generic pixel-contiguous GEMM ----------------
// thread: 4 pixels x 4 outputs. blockDim=64. grid: (LL/256, ceil(M/4), NB)
// input batch index = blockIdx.z >> inShift (lets 4 directions share one input)
__global__ void gemm_pw(const float* __restrict__ in, size_t inStride,
                        const float* __restrict__ W, const float* __restrict__ bias,
                        float* __restrict__ out, size_t outStride,
                        int M, int KK, int perBatchW, int act, int accum, int inShift)
{
    extern __shared__ float sW[];
    int bb = blockIdx.z;
    int wsel = perBatchW ? (bb & 3) : 0;
    int co0 = blockIdx.y * 4;
    const float* Wp = W + (size_t)wsel * M * KK;
    for (int i = threadIdx.x; i < 4 * KK; i += blockDim.x) {
        int co = co0 + i / KK;
        sW[i] = (co < M) ? Wp[(size_t)co * KK + (i % KK)] : 0.f;
    }
    __syncthreads();
    int pix = blockIdx.x * 256 + threadIdx.x * 4;
    const float* ip = in + (size_t)(bb >> inShift) * inStride + pix;
    float4 acc[4];
#pragma unroll
    for (int j = 0; j < 4; j++) {
        float bv = 0.f;
        if (bias != nullptr && (co0 + j) < M) bv = bias[wsel * M + co0 + j];
        acc[j] = make_float4(bv, bv, bv, bv);
    }
#pragma unroll 8
    for (int ci = 0; ci < KK; ci++) {
        float4 v = *reinterpret_cast<const float4*>(ip + (size_t)ci * LL);
#pragma unroll
        for (int j = 0; j < 4; j++) {
            float w = sW[j * KK + ci];
            acc[j].x = fmaf(w, v.x, acc[j].x);
            acc[j].y = fmaf(w, v.y, acc[j].y);
            acc[j].z = fmaf(w, v.z, acc[j].z);
            acc[j].w = fmaf(w, v.w, acc[j].w);
        }
    }
#pragma unroll
    for (int j = 0; j < 4; j++) {
        int co = co0 + j;
        if (co >= M) continue;
        float4 r = acc[j];
        if (act == 1) {
            r.x = softplusf(r.x); r.y = softplusf(r.y);
            r.z = softplusf(r.z); r.w = softplusf(r.w);
        }
        float* op = out + (size_t)bb * outStride + (size_t)co * LL + pix;
        if (accum) {
            float4 o = *reinterpret_cast<const float4*>(op);
            r.x += o.x; r.y += o.y; r.z += o.z; r.w += o.w;
        }
        *reinterpret_cast<float4*>(op) = r;
    }
}

// ---------------- fused 6x depthwise dilated conv + BN ----------------
__global__ void dwconv6_kernel(const float* __restrict__ lk_w, const float* __restrict__ lk_bn,
                               const float* __restrict__ b0w, const float* __restrict__ b1w,
                               const float* __restrict__ b2w, const float* __restrict__ b3w,
                               const float* __restrict__ b4w, const float* __restrict__ br_bn)
{
    __shared__ float sIn[44 * 44];
    __shared__ float sWt[270];
    int bc = blockIdx.z;
    int c = bc % CH;
    int h0 = blockIdx.y * 32;
    int w0 = blockIdx.x * 32;
    const float* in = g_y + (size_t)bc * LL;
    int tid = threadIdx.y * 32 + threadIdx.x;

    float s_lk = lk_bn[c] * rsqrtf(lk_bn[3 * CH + c] + 1e-5f);
    float sbr[5];
#pragma unroll
    for (int i = 0; i < 5; i++)
        sbr[i] = br_bn[(i * 4 + 0) * CH + c] * rsqrtf(br_bn[(i * 4 + 3) * CH + c] + 1e-5f);

    for (int i = tid; i < 270; i += 256) {
        float w;
        if (i < 169)      w = lk_w[c * 169 + i] * s_lk;
        else if (i < 194) w = b0w[c * 25 + (i - 169)] * sbr[0];
        else if (i < 243) w = b1w[c * 49 + (i - 194)] * sbr[1];
        else if (i < 252) w = b2w[c * 9 + (i - 243)] * sbr[2];
        else if (i < 261) w = b3w[c * 9 + (i - 252)] * sbr[3];
        else              w = b4w[c * 9 + (i - 261)] * sbr[4];
        sWt[i] = w;
    }
    for (int i = tid; i < 44 * 44; i += 256) {
        int r = i / 44, cl = i % 44;
        int gh = h0 - 6 + r, gw = w0 - 6 + cl;
        float v = 0.f;
        if (gh >= 0 && gh < HH && gw >= 0 && gw < WW) v = in[gh * WW + gw];
        sIn[i] = v;
    }
    __syncthreads();

    int tx = threadIdx.x, ty = threadIdx.y;
    float a0 = 0.f, a1 = 0.f, a2 = 0.f, a3 = 0.f;
    const float* base = sIn + (ty + 6) * 44 + (tx + 6);

#pragma unroll 1
    for (int ky = 0; ky < 13; ky++) {
        const float* rp = base + (ky - 6) * 44;
#pragma unroll
        for (int kx = 0; kx < 13; kx++) {
            float w = sWt[ky * 13 + kx];
            int dx = kx - 6;
            a0 = fmaf(w, rp[dx], a0);
            a1 = fmaf(w, rp[dx + 352], a1);
            a2 = fmaf(w, rp[dx + 704], a2);
            a3 = fmaf(w, rp[dx + 1056], a3);
        }
    }
#define BRANCH(KSZ, DIL, OFF) \
    { const int hk = (KSZ - 1) / 2; \
      _Pragma("unroll 1") \
      for (int ky = 0; ky < KSZ; ky++) { \
          const float* rp = base + (ky - hk) * DIL * 44; \
          _Pragma("unroll") \
          for (int kx = 0; kx < KSZ; kx++) { \
              float w = sWt[OFF + ky * KSZ + kx]; \
              int dx = (kx - hk) * DIL; \
              a0 = fmaf(w, rp[dx], a0); \
              a1 = fmaf(w, rp[dx + 352], a1); \
              a2 = fmaf(w, rp[dx + 704], a2); \
              a3 = fmaf(w, rp[dx + 1056], a3); \
          } } }
    BRANCH(5, 1, 169)
    BRANCH(7, 2, 194)
    BRANCH(3, 3, 243)
    BRANCH(3, 4, 252)
    BRANCH(3, 5, 261)
#undef BRANCH

    float T = lk_bn[CH + c] - lk_bn[2 * CH + c] * s_lk;
#pragma unroll
    for (int i = 0; i < 5; i++)
        T += br_bn[(i * 4 + 1) * CH + c] - br_bn[(i * 4 + 2) * CH + c] * sbr[i];

    float* op = g_dr + (size_t)bc * LL;
    op[(h0 + ty + 0) * WW + w0 + tx]  = a0 + T;
    op[(h0 + ty + 8) * WW + w0 + tx]  = a1 + T;
    op[(h0 + ty + 16) * WW + w0 + tx] = a2 + T;
    op[(h0 + ty + 24) * WW + w0 + tx] = a3 + T;
}

// ---------------- 3x3 depthwise conv + bias + silu on xp ----------------
__global__ void dwconv3_silu_kernel(const float* __restrict__ dw_w, const float* __restrict__ dw_b)
{
    __shared__ float sIn[10 * 66];
    int bc = blockIdx.z;
    int c = bc % CH;
    int b = bc / CH;
    int h0 = blockIdx.y * 8;
    const float* in = g_xz + ((size_t)b * FGC + c) * LL;
    int tid = threadIdx.y * 64 + threadIdx.x;
    for (int i = tid; i < 10 * 66; i += 512) {
        int r = i / 66, cl = i % 66;
        int gh = h0 - 1 + r, gw = -1 + cl;
        sIn[i] = (gh >= 0 && gh < HH && gw >= 0 && gw < WW) ? in[gh * WW + gw] : 0.f;
    }
    float wreg[9];
#pragma unroll
    for (int i = 0; i < 9; i++) wreg[i] = dw_w[c * 9 + i];
    __syncthreads();
    int tx = threadIdx.x, ty = threadIdx.y;
    float a = dw_b[c];
#pragma unroll
    for (int ky = 0; ky < 3; ky++)
#pragma unroll
        for (int kx = 0; kx < 3; kx++)
            a = fmaf(wreg[ky * 3 + kx], sIn[(ty + ky) * 66 + tx + kx], a);
    g_xc[(size_t)bc * LL + (h0 + ty) * WW + tx] = siluf(a);
}

// ---------------- repack B/C rows of dblhw into scan-order [l][n] ----------------
__global__ void repack_kernel()
{
    __shared__ float sB[16][33], sC[16][33];
    int bk = blockIdx.y;
    int k = bk & 3;
    int l0 = blockIdx.x * 32;
    int tid = threadIdx.x;
    int n = tid >> 5, i = tid & 31;
    const float* dp = g_dbl + (size_t)bk * DBLR * LL;
    int ml = mapk(k, l0 + i);
    sB[n][i] = dp[(size_t)(RKN + n) * LL + ml];
    sC[n][i] = dp[(size_t)(RKN + NST + n) * LL + ml];
    __syncthreads();
    int li = tid >> 4, n2 = tid & 15;
    size_t o = (size_t)bk * LL * NST + (size_t)(l0 + li) * NST + n2;
    g_Bt[o] = sB[n2][li];
    g_Ct[o] = sC[n2][li];
}

// ---------------- scan pass 1: per-chunk transforms (E,F) ----------------
// block = 256 thr = 16 channels (half-warp groups) x one (bk, chunk).
// All groups share the same Bt addresses -> L1 hits.
// grid: (CH/16, NCHUNK, BB*KD)
__global__ void scan_pass1(const float* __restrict__ A_log)
{
    int bk = blockIdx.z;
    int k = bk & 3;
    int b = bk >> 2;
    int gch = blockIdx.y;            // chunk index
    int c = blockIdx.x * 16 + (threadIdx.x >> 4);
    int n = threadIdx.x & 15;

    float A = -__expf(A_log[(size_t)(k * CH + c) * NST + n]);
    const float* __restrict__ dp = g_delta + (size_t)(bk * CH + c) * LL;
    const float* __restrict__ up = g_xc + (size_t)(b * CH + c) * LL;
    const float* __restrict__ Bp = g_Bt + (size_t)bk * LL * NST;
    int l0 = gch * CHUNK;

    float E = 1.f, F = 0.f;
#pragma unroll 4
    for (int i = 0; i < CHUNK; i++) {
        int l = l0 + i;
        int ml = mapk(k, l);
        float dl = dp[ml];
        float uu = up[ml];
        float Bv = Bp[(size_t)l * NST + n];
        float e = __expf(dl * A);
        F = fmaf(e, F, dl * uu * Bv);
        E *= e;
    }
    size_t o = (size_t)((bk * CH + c) * NCHUNK + gch) * 2 * NST + n;
    g_EF[o] = E;
    g_EF[o + NST] = F;
}

// ---------------- scan pass 2: prefix + replay + mapped y write ----------------
__global__ void scan_pass2(const float* __restrict__ A_log, const float* __restrict__ Ds)
{
    __shared__ float y_s[16 * 257];
    int bk = blockIdx.z;
    int k = bk & 3;
    int b = bk >> 2;
    int gch = blockIdx.y;
    int grp = threadIdx.x >> 4;
    int c = blockIdx.x * 16 + grp;
    int n = threadIdx.x & 15;

    float A = -__expf(A_log[(size_t)(k * CH + c) * NST + n]);
    float D = Ds[k * CH + c];
    const float* __restrict__ dp = g_delta + (size_t)(bk * CH + c) * LL;
    const float* __restrict__ up = g_xc + (size_t)(b * CH + c) * LL;
    const float* __restrict__ Bp = g_Bt + (size_t)bk * LL * NST;
    const float* __restrict__ Cp = g_Ct + (size_t)bk * LL * NST;
    int l0 = gch * CHUNK;

    // h0 = composition of chunks 0..gch-1
    float h = 0.f;
    const float* efp = g_EF + (size_t)(bk * CH + c) * NCHUNK * 2 * NST + n;
    for (int j = 0; j < gch; j++) {
        float Ej = efp[(size_t)j * 2 * NST];
        float Fj = efp[(size_t)j * 2 * NST + NST];
        h = fmaf(Ej, h, Fj);
    }

#pragma unroll 4
    for (int i = 0; i < CHUNK; i++) {
        int l = l0 + i;
        int ml = mapk(k, l);
        float dl = dp[ml];
        float uu = up[ml];
        float Bv = Bp[(size_t)l * NST + n];
        float Cv = Cp[(size_t)l * NST + n];
        float e = __expf(dl * A);
        h = fmaf(e, h, dl * uu * Bv);
        float tt = h * Cv;
#pragma unroll
        for (int off = 1; off < 16; off <<= 1)
            tt += __shfl_xor_sync(0xffffffffu, tt, off);
        if (n == 0) y_s[grp * 257 + i] = tt + D * uu;
    }
    __syncthreads();

    // cooperative mapped write (semi-coalesced for all directions)
    float* yout = g_ys + (size_t)(bk * CH + blockIdx.x * 16) * LL;
    int tid = threadIdx.x;
    if ((k & 1) == 0) {
        for (int idx = tid; idx < 16 * 256; idx += 256) {
            int cl = idx >> 8, i = idx & 255;
            int tgt = mapk(k, l0 + i);   // contiguous in i
            yout[(size_t)cl * LL + tgt] = y_s[cl * 257 + i];
        }
    } else {
        for (int idx = tid; idx < 16 * 256; idx += 256) {
            int cl = idx >> 8;
            int rem = idx & 255;
            int hh = rem >> 2, j = rem & 3;
            int sl = j * 64 + hh;        // local scan index
            int tgt = mapk(k, l0 + sl);  // 16B-contiguous in j
            yout[(size_t)cl * LL + tgt] = y_s[cl * 257 + sl];
        }
    }
}

// ---------------- LayerNorm over channel + combine(4 dirs) + silu(z) gate ----------------
__global__ void ln_gate_kernel(const float* __restrict__ ln_g, const float* __restrict__ ln_b)
{
    __shared__ float sY[CH * 33];
    __shared__ float sZ[CH * 33];
    int b = blockIdx.y;
    int l0 = blockIdx.x * 32;
    int tid = threadIdx.x;
    const float* y0p = g_ys + (size_t)(b * KD + 0) * CH * LL;
    const float* y1p = g_ys + (size_t)(b * KD + 1) * CH * LL;
    const float* y2p = g_ys + (size_t)(b * KD + 2) * CH * LL;
    const float* y3p = g_ys + (size_t)(b * KD + 3) * CH * LL;
    const float* zp = g_xz + ((size_t)b * FGC + CH) * LL;
    for (int i = tid; i < CH * 32; i += 256) {
        int cc = i >> 5, ii = i & 31;
        size_t o = (size_t)cc * LL + l0 + ii;
        sY[cc * 33 + ii] = y0p[o] + y1p[o] + y2p[o] + y3p[o];
        sZ[cc * 33 + ii] = zp[o];
    }
    __syncthreads();
    int warp = tid >> 5, lane = tid & 31;
    float g0 = ln_g[lane], g1 = ln_g[lane + 32], g2 = ln_g[lane + 64];
    float bb0 = ln_b[lane], bb1 = ln_b[lane + 32], bb2 = ln_b[lane + 64];
    for (int q = 0; q < 4; q++) {
        int i = warp * 4 + q;
        float y0 = sY[lane * 33 + i], y1 = sY[(lane + 32) * 33 + i], y2 = sY[(lane + 64) * 33 + i];
        float s = y0 + y1 + y2;
        float ss = y0 * y0 + y1 * y1 + y2 * y2;
#pragma unroll
        for (int off = 16; off; off >>= 1) {
            s += __shfl_xor_sync(0xffffffffu, s, off);
            ss += __shfl_xor_sync(0xffffffffu, ss, off);
        }
        float mean = s * (1.f / 96.f);
        float var = ss * (1.f / 96.f) - mean * mean;
        float rs = rsqrtf(var + 1e-5f);
        float z0 = sZ[lane * 33 + i], z1 = sZ[(lane + 32) * 33 + i], z2 = sZ[(lane + 64) * 33 + i];
        float r0 = ((y0 - mean) * rs * g0 + bb0) * siluf(z0);
        float r1 = ((y1 - mean) * rs * g1 + bb1) * siluf(z1);
        float r2 = ((y2 - mean) * rs * g2 + bb2) * siluf(z2);
        sY[lane * 33 + i] = r0;
        sY[(lane + 32) * 33 + i] = r1;
        sY[(lane + 64) * 33 + i] = r2;
    }
    __syncthreads();
    float* op = g_yln + (size_t)b * CH * LL;
    for (int i = tid; i < CH * 32; i += 256) {
        int cc = i >> 5, ii = i & 31;
        op[(size_t)cc * LL + l0 + ii] = sY[cc * 33 + ii];
    }
}

// ---------------- psi gate: sigmoid(bn(conv1x1(relu(y)))) ----------------
__global__ void psi_kernel(const float* __restrict__ psi_w, const float* __restrict__ psi_b,
                           const float* __restrict__ psi_bn)
{
    int idx = blockIdx.x * blockDim.x + threadIdx.x;
    if (idx >= BB * LL) return;
    int b = idx / LL, l = idx % LL;
    const float* yp = g_y + (size_t)b * CH * LL + l;
    float acc = psi_b[0];
#pragma unroll 4
    for (int cc = 0; cc < CH; cc++)
        acc = fmaf(psi_w[cc], fmaxf(yp[(size_t)cc * LL], 0.f), acc);
    float s = psi_bn[0] * rsqrtf(psi_bn[3] + 1e-5f);
    float v = (acc - psi_bn[2]) * s + psi_bn[1];
    g_p[idx] = 1.f / (1.f + __expf(-v));
}

// ---------------- final: out = p*x + relu(ss) ----------------
__global__ void final_kernel(const float* __restrict__ x, float* __restrict__ out)
{
    int i4 = blockIdx.x * blockDim.x + threadIdx.x;
    if (i4 >= BB * CH * LL / 4) return;
    int idx = i4 * 4;
    int b = idx / (CH * LL);
    int l = idx % LL;
    float4 xv = *reinterpret_cast<const float4*>(x + idx);
    float4 sv = *reinterpret_cast<const float4*>(g_ss + idx);
    float4 pv = *reinterpret_cast<const float4*>(g_p + (size_t)b * LL + l);
    float4 o;
    o.x = pv.x * xv.x + fmaxf(sv.x, 0.f);
    o.y = pv.y * xv.y + fmaxf(sv.y, 0.f);
    o.z = pv.z * xv.z + fmaxf(sv.z, 0.f);
    o.w = pv.w * xv.w + fmaxf(sv.w, 0.f);
    *reinterpret_cast<float4*>(out + idx) = o;
}

// ---------------- host launch ----------------
extern "C" void kernel_launch(void* const* d_in, const int* in_sizes, int n_in,
                              void* d_out, int out_size)
{
    const float* g        = (const float*)d_in[0];
    const float* x        = (const float*)d_in[1];
    const float* wg_w     = (const float*)d_in[2];
    const float* wg_b     = (const float*)d_in[3];
    const float* wx_w     = (const float*)d_in[4];
    const float* wx_b     = (const float*)d_in[5];
    const float* psi_w    = (const float*)d_in[6];
    const float* psi_b    = (const float*)d_in[7];
    const float* psi_bn   = (const float*)d_in[8];
    const float* lk_w     = (const float*)d_in[9];
    const float* lk_bn    = (const float*)d_in[10];
    const float* br0      = (const float*)d_in[11];
    const float* br1      = (const float*)d_in[12];
    const float* br2      = (const float*)d_in[13];
    const float* br3      = (const float*)d_in[14];
    const float* br4      = (const float*)d_in[15];
    const float* br_bn    = (const float*)d_in[16];
    const float* in_proj_w= (const float*)d_in[17];
    const float* dw_w     = (const float*)d_in[18];
    const float* dw_b     = (const float*)d_in[19];
    const float* xproj_w  = (const float*)d_in[20];
    const float* dtproj_w = (const float*)d_in[21];
    const float* dtproj_b = (const float*)d_in[22];
    const float* A_log    = (const float*)d_in[23];
    const float* Ds       = (const float*)d_in[24];
    const float* ln_g     = (const float*)d_in[25];
    const float* ln_b     = (const float*)d_in[26];
    const float* outp_w   = (const float*)d_in[27];

    float *py, *pdr, *pxz, *pxc, *pdbl, *pdelta, *pyln, *pss;
    cudaGetSymbolAddress((void**)&py, g_y);
    cudaGetSymbolAddress((void**)&pdr, g_dr);
    cudaGetSymbolAddress((void**)&pxz, g_xz);
    cudaGetSymbolAddress((void**)&pxc, g_xc);
    cudaGetSymbolAddress((void**)&pdbl, g_dbl);
    cudaGetSymbolAddress((void**)&pdelta, g_delta);
    cudaGetSymbolAddress((void**)&pyln, g_yln);
    cudaGetSymbolAddress((void**)&pss, g_ss);

    // 1-2: y = conv1x1(g) + conv1x1(x)
    gemm_pw<<<dim3(16, 24, BB), 64, 4 * 192 * 4>>>(g, (size_t)FGC * LL, wg_w, wg_b,
                                                   py, (size_t)CH * LL, CH, FGC, 0, 0, 0, 0);
    gemm_pw<<<dim3(16, 24, BB), 64, 4 * 96 * 4>>>(x, (size_t)CH * LL, wx_w, wx_b,
                                                  py, (size_t)CH * LL, CH, CH, 0, 0, 1, 0);
    // 3: fused 6 depthwise convs + BN -> dr
    dwconv6_kernel<<<dim3(2, 2, BB * CH), dim3(32, 8)>>>(lk_w, lk_bn, br0, br1, br2, br3, br4, br_bn);
    // 4: in_proj -> xz
    gemm_pw<<<dim3(16, 48, BB), 64, 4 * 96 * 4>>>(pdr, (size_t)CH * LL, in_proj_w, nullptr,
                                                  pxz, (size_t)FGC * LL, FGC, CH, 0, 0, 0, 0);
    // 5: depthwise 3x3 + silu -> xc (hw order; directions handled by index maps)
    dwconv3_silu_kernel<<<dim3(1, 8, BB * CH), dim3(64, 8)>>>(dw_w, dw_b);
    // 6: xproj (per-direction weights, shared hw-order input)
    gemm_pw<<<dim3(16, 10, BB * KD), 64, 4 * 96 * 4>>>(pxc, (size_t)CH * LL, xproj_w, nullptr,
                                                       pdbl, (size_t)DBLR * LL, DBLR, CH, 1, 0, 0, 2);
    // 7: repack B/C into scan-order [l][n]
    repack_kernel<<<dim3(LL / 32, BB * KD), 512>>>();
    // 8: dtproj + softplus -> delta (hw order)
    gemm_pw<<<dim3(16, 24, BB * KD), 64, 4 * 6 * 4>>>(pdbl, (size_t)DBLR * LL, dtproj_w, dtproj_b,
                                                      pdelta, (size_t)CH * LL, CH, RKN, 1, 1, 0, 0);
    // 9-10: selective scan (chunk transforms, then prefix+replay+mapped write)
    scan_pass1<<<dim3(CH / 16, NCHUNK, BB * KD), 256>>>(A_log);
    scan_pass2<<<dim3(CH / 16, NCHUNK, BB * KD), 256>>>(A_log, Ds);
    // 11: LN + combine + silu gate
    ln_gate_kernel<<<dim3(LL / 32, BB), 256>>>(ln_g, ln_b);
    // 12: out_proj -> ss
    gemm_pw<<<dim3(16, 24, BB), 64, 4 * 96 * 4>>>(pyln, (size_t)CH * LL, outp_w, nullptr,
                                                  pss, (size_t)CH * LL, CH, CH, 0, 0, 0, 0);
    // 13: psi gate
    psi_kernel<<<(BB * LL + 255) / 256, 256>>>(psi_w, psi_b, psi_bn);
    // 14: final
    final_kernel<<<(BB * CH * LL / 4 + 255) / 256, 256>>>(x, (float*)d_out);
}

// round 7
// speedup vs baseline: 4.5843x; 1.1677x over previous
#include <cuda_runtime.h>
#include <math.h>

#define BB 2
#define CH 96
#define FGC 192
#define HH 64
#define WW 64
#define LL 4096
#define NST 16
#define RKN 6
#define KD 4
#define DBLR 38
#define CHUNK 256
#define NCHUNK 16
#define PXB 128
#define COB 16
#define KS 32

// ---------------- scratch (static device globals; no allocations) ----------------
__device__ float g_y[BB*CH*LL];
__device__ float g_dr[BB*CH*LL];
__device__ float g_xz[BB*2*CH*LL];
__device__ float g_xc[BB*CH*LL];
__device__ float g_xcT[BB*CH*LL];
__device__ float g_dbl[BB*KD*DBLR*LL];
__device__ float g_Bt[BB*KD*LL*NST];
__device__ float g_Ct[BB*KD*LL*NST];
__device__ float g_delta[BB*KD*CH*LL];
__device__ float g_dT[BB*2*CH*LL];
__device__ float g_ys[BB*KD*CH*LL];
__device__ float g_EF[BB*KD*CH*NCHUNK*2*NST];
__device__ float g_yln[BB*CH*LL];
__device__ float g_ss[BB*CH*LL];
__device__ float g_p[BB*LL];

__device__ __forceinline__ float softplusf(float x) {
    return (x > 20.f) ? x : log1pf(__expf(x));
}
__device__ __forceinline__ float siluf(float x) {
    return x / (1.f + __expf(-x));
}
// scan-order l -> hw-order index for direction k
__device__ __forceinline__ int mapk(int k, int l) {
    int l2 = (k & 2) ? (4095 - l) : l;
    return (k & 1) ? (((l2 & 63) << 6) | (l2 >> 6)) : l2;
}

// ---------------- smem-tiled GEMM ----------------
// out[bb][co][px] = sum_ci W[co][ci]*in[ci][px] (+bias1+bias2), two-phase K (A then B).
// block 256 thr = 32 px-quads x 8 co-pairs. COB=16 outputs, PXB=128 pixels per block.
__global__ void gemm_tiled(const float* __restrict__ inA, size_t strideA, int K1,
                           const float* __restrict__ WA,
                           const float* __restrict__ inB, size_t strideB, int K2,
                           const float* __restrict__ WB,
                           const float* __restrict__ bias1, const float* __restrict__ bias2,
                           float* __restrict__ out, size_t outStride,
                           int M, int perBatchW, int inShift)
{
    __shared__ float sIn[KS * PXB];   // 16 KB
    __shared__ float sW[COB * KS];    // 2 KB
    int bb = blockIdx.z;
    int ib = bb >> inShift;
    int wsel = perBatchW ? (bb & 3) : 0;
    int px0 = blockIdx.x * PXB;
    int co0 = blockIdx.y * COB;
    int tid = threadIdx.x;
    int quad = tid & 31;
    int cog = tid >> 5;

    float4 acc[2];
    acc[0] = make_float4(0.f, 0.f, 0.f, 0.f);
    acc[1] = make_float4(0.f, 0.f, 0.f, 0.f);

    int nslice = (K1 + K2) / KS;
    for (int s = 0; s < nslice; s++) {
        int ks = s * KS;
        const float* ip;
        const float* wp;
        int kbase, KKcur;
        if (ks < K1) {
            ip = inA + (size_t)ib * strideA;
            wp = WA + (size_t)wsel * M * K1;
            kbase = ks; KKcur = K1;
        } else {
            ip = inB + (size_t)ib * strideB;
            wp = WB;
            kbase = ks - K1; KKcur = K2;
        }
        // stage input slice: KS rows x PXB px = 1024 float4, 4 per thread
#pragma unroll
        for (int t = 0; t < 4; t++) {
            int idx = tid + t * 256;
            int row = idx >> 5, c4 = idx & 31;
            *reinterpret_cast<float4*>(&sIn[row * PXB + c4 * 4]) =
                *reinterpret_cast<const float4*>(ip + (size_t)(kbase + row) * LL + px0 + c4 * 4);
        }
        // stage weight slice: COB rows x KS = 128 float4, threads 0..127
        if (tid < COB * KS / 4) {
            int r = tid >> 3, c4 = tid & 7;
            int co = co0 + r;
            float4 wv = make_float4(0.f, 0.f, 0.f, 0.f);
            if (co < M)
                wv = *reinterpret_cast<const float4*>(wp + (size_t)co * KKcur + kbase + c4 * 4);
            *reinterpret_cast<float4*>(&sW[r * KS + c4 * 4]) = wv;
        }
        __syncthreads();
#pragma unroll
        for (int ci = 0; ci < KS; ci++) {
            float4 v = *reinterpret_cast<const float4*>(&sIn[ci * PXB + quad * 4]);
#pragma unroll
            for (int j = 0; j < 2; j++) {
                float w = sW[(cog * 2 + j) * KS + ci];
                acc[j].x = fmaf(w, v.x, acc[j].x);
                acc[j].y = fmaf(w, v.y, acc[j].y);
                acc[j].z = fmaf(w, v.z, acc[j].z);
                acc[j].w = fmaf(w, v.w, acc[j].w);
            }
        }
        __syncthreads();
    }
#pragma unroll
    for (int j = 0; j < 2; j++) {
        int co = co0 + cog * 2 + j;
        if (co >= M) continue;
        float bv = 0.f;
        if (bias1 != nullptr) bv += bias1[co];
        if (bias2 != nullptr) bv += bias2[co];
        float4 r = acc[j];
        r.x += bv; r.y += bv; r.z += bv; r.w += bv;
        *reinterpret_cast<float4*>(out + (size_t)bb * outStride + (size_t)co * LL + px0 + quad * 4) = r;
    }
}

// ---------------- small-K GEMM (dtproj: K=6) ----------------
__global__ void gemm_pw(const float* __restrict__ in, size_t inStride,
                        const float* __restrict__ W, const float* __restrict__ bias,
                        float* __restrict__ out, size_t outStride,
                        int M, int KK, int perBatchW, int act, int accum, int inShift)
{
    extern __shared__ float sW[];
    int bb = blockIdx.z;
    int wsel = perBatchW ? (bb & 3) : 0;
    int co0 = blockIdx.y * 4;
    const float* Wp = W + (size_t)wsel * M * KK;
    for (int i = threadIdx.x; i < 4 * KK; i += blockDim.x) {
        int co = co0 + i / KK;
        sW[i] = (co < M) ? Wp[(size_t)co * KK + (i % KK)] : 0.f;
    }
    __syncthreads();
    int pix = blockIdx.x * 256 + threadIdx.x * 4;
    const float* ip = in + (size_t)(bb >> inShift) * inStride + pix;
    float4 acc[4];
#pragma unroll
    for (int j = 0; j < 4; j++) {
        float bv = 0.f;
        if (bias != nullptr && (co0 + j) < M) bv = bias[wsel * M + co0 + j];
        acc[j] = make_float4(bv, bv, bv, bv);
    }
#pragma unroll 8
    for (int ci = 0; ci < KK; ci++) {
        float4 v = *reinterpret_cast<const float4*>(ip + (size_t)ci * LL);
#pragma unroll
        for (int j = 0; j < 4; j++) {
            float w = sW[j * KK + ci];
            acc[j].x = fmaf(w, v.x, acc[j].x);
            acc[j].y = fmaf(w, v.y, acc[j].y);
            acc[j].z = fmaf(w, v.z, acc[j].z);
            acc[j].w = fmaf(w, v.w, acc[j].w);
        }
    }
#pragma unroll
    for (int j = 0; j < 4; j++) {
        int co = co0 + j;
        if (co >= M) continue;
        float4 r = acc[j];
        if (act == 1) {
            r.x = softplusf(r.x); r.y = softplusf(r.y);
            r.z = softplusf(r.z); r.w = softplusf(r.w);
        }
        float* op = out + (size_t)bb * outStride + (size_t)co * LL + pix;
        if (accum) {
            float4 o = *reinterpret_cast<const float4*>(op);
            r.x += o.x; r.y += o.y; r.z += o.z; r.w += o.w;
        }
        *reinterpret_cast<float4*>(op) = r;
    }
}

// ---------------- fused 6x depthwise dilated conv + BN ----------------
__global__ void dwconv6_kernel(const float* __restrict__ lk_w, const float* __restrict__ lk_bn,
                               const float* __restrict__ b0w, const float* __restrict__ b1w,
                               const float* __restrict__ b2w, const float* __restrict__ b3w,
                               const float* __restrict__ b4w, const float* __restrict__ br_bn)
{
    __shared__ float sIn[44 * 44];
    __shared__ float sWt[270];
    int bc = blockIdx.z;
    int c = bc % CH;
    int h0 = blockIdx.y * 32;
    int w0 = blockIdx.x * 32;
    const float* in = g_y + (size_t)bc * LL;
    int tid = threadIdx.y * 32 + threadIdx.x;

    float s_lk = lk_bn[c] * rsqrtf(lk_bn[3 * CH + c] + 1e-5f);
    float sbr[5];
#pragma unroll
    for (int i = 0; i < 5; i++)
        sbr[i] = br_bn[(i * 4 + 0) * CH + c] * rsqrtf(br_bn[(i * 4 + 3) * CH + c] + 1e-5f);

    for (int i = tid; i < 270; i += 256) {
        float w;
        if (i < 169)      w = lk_w[c * 169 + i] * s_lk;
        else if (i < 194) w = b0w[c * 25 + (i - 169)] * sbr[0];
        else if (i < 243) w = b1w[c * 49 + (i - 194)] * sbr[1];
        else if (i < 252) w = b2w[c * 9 + (i - 243)] * sbr[2];
        else if (i < 261) w = b3w[c * 9 + (i - 252)] * sbr[3];
        else              w = b4w[c * 9 + (i - 261)] * sbr[4];
        sWt[i] = w;
    }
    for (int i = tid; i < 44 * 44; i += 256) {
        int r = i / 44, cl = i % 44;
        int gh = h0 - 6 + r, gw = w0 - 6 + cl;
        float v = 0.f;
        if (gh >= 0 && gh < HH && gw >= 0 && gw < WW) v = in[gh * WW + gw];
        sIn[i] = v;
    }
    __syncthreads();

    int tx = threadIdx.x, ty = threadIdx.y;
    float a0 = 0.f, a1 = 0.f, a2 = 0.f, a3 = 0.f;
    const float* base = sIn + (ty + 6) * 44 + (tx + 6);

#pragma unroll 1
    for (int ky = 0; ky < 13; ky++) {
        const float* rp = base + (ky - 6) * 44;
#pragma unroll
        for (int kx = 0; kx < 13; kx++) {
            float w = sWt[ky * 13 + kx];
            int dx = kx - 6;
            a0 = fmaf(w, rp[dx], a0);
            a1 = fmaf(w, rp[dx + 352], a1);
            a2 = fmaf(w, rp[dx + 704], a2);
            a3 = fmaf(w, rp[dx + 1056], a3);
        }
    }
#define BRANCH(KSZ, DIL, OFF) \
    { const int hk = (KSZ - 1) / 2; \
      _Pragma("unroll 1") \
      for (int ky = 0; ky < KSZ; ky++) { \
          const float* rp = base + (ky - hk) * DIL * 44; \
          _Pragma("unroll") \
          for (int kx = 0; kx < KSZ; kx++) { \
              float w = sWt[OFF + ky * KSZ + kx]; \
              int dx = (kx - hk) * DIL; \
              a0 = fmaf(w, rp[dx], a0); \
              a1 = fmaf(w, rp[dx + 352], a1); \
              a2 = fmaf(w, rp[dx + 704], a2); \
              a3 = fmaf(w, rp[dx + 1056], a3); \
          } } }
    BRANCH(5, 1, 169)
    BRANCH(7, 2, 194)
    BRANCH(3, 3, 243)
    BRANCH(3, 4, 252)
    BRANCH(3, 5, 261)
#undef BRANCH

    float T = lk_bn[CH + c] - lk_bn[2 * CH + c] * s_lk;
#pragma unroll
    for (int i = 0; i < 5; i++)
        T += br_bn[(i * 4 + 1) * CH + c] - br_bn[(i * 4 + 2) * CH + c] * sbr[i];

    float* op = g_dr + (size_t)bc * LL;
    op[(h0 + ty + 0) * WW + w0 + tx]  = a0 + T;
    op[(h0 + ty + 8) * WW + w0 + tx]  = a1 + T;
    op[(h0 + ty + 16) * WW + w0 + tx] = a2 + T;
    op[(h0 + ty + 24) * WW + w0 + tx] = a3 + T;
}

// ---------------- 3x3 depthwise conv + bias + silu on xp ----------------
__global__ void dwconv3_silu_kernel(const float* __restrict__ dw_w, const float* __restrict__ dw_b)
{
    __shared__ float sIn[10 * 66];
    int bc = blockIdx.z;
    int c = bc % CH;
    int b = bc / CH;
    int h0 = blockIdx.y * 8;
    const float* in = g_xz + ((size_t)b * FGC + c) * LL;
    int tid = threadIdx.y * 64 + threadIdx.x;
    for (int i = tid; i < 10 * 66; i += 512) {
        int r = i / 66, cl = i % 66;
        int gh = h0 - 1 + r, gw = -1 + cl;
        sIn[i] = (gh >= 0 && gh < HH && gw >= 0 && gw < WW) ? in[gh * WW + gw] : 0.f;
    }
    float wreg[9];
#pragma unroll
    for (int i = 0; i < 9; i++) wreg[i] = dw_w[c * 9 + i];
    __syncthreads();
    int tx = threadIdx.x, ty = threadIdx.y;
    float a = dw_b[c];
#pragma unroll
    for (int ky = 0; ky < 3; ky++)
#pragma unroll
        for (int kx = 0; kx < 3; kx++)
            a = fmaf(wreg[ky * 3 + kx], sIn[(ty + ky) * 66 + tx + kx], a);
    g_xc[(size_t)bc * LL + (h0 + ty) * WW + tx] = siluf(a);
}

// ---------------- transpose 64x64 planes: xc -> xcT, delta(odd k) -> dT ----------------
__global__ void transpose_kernel()
{
    __shared__ float s[64][65];
    int p = blockIdx.x;
    const float* in;
    float* out;
    if (p < BB * CH) {
        in = g_xc + (size_t)p * LL;
        out = g_xcT + (size_t)p * LL;
    } else {
        int q = p - BB * CH;
        int j = q / CH;              // 0..3: (b, k=1 or 3)
        int c = q % CH;
        int b = j >> 1;
        int kk = (j & 1) ? 3 : 1;
        in = g_delta + ((size_t)(b * KD + kk) * CH + c) * LL;
        out = g_dT + ((size_t)(b * 2 + (j & 1)) * CH + c) * LL;
    }
    int tid = threadIdx.x;
    for (int i = tid; i < 4096; i += 256) {
        s[i >> 6][i & 63] = in[i];
    }
    __syncthreads();
    for (int i = tid; i < 4096; i += 256) {
        out[i] = s[i & 63][i >> 6];
    }
}

// ---------------- repack B/C rows of dbl into scan-order [l][n] ----------------
__global__ void repack_kernel()
{
    __shared__ float sB[16][33], sC[16][33];
    int bk = blockIdx.y;
    int k = bk & 3;
    int l0 = blockIdx.x * 32;
    int tid = threadIdx.x;
    int n = tid >> 5, i = tid & 31;
    const float* dp = g_dbl + (size_t)bk * DBLR * LL;
    int ml = mapk(k, l0 + i);
    sB[n][i] = dp[(size_t)(RKN + n) * LL + ml];
    sC[n][i] = dp[(size_t)(RKN + NST + n) * LL + ml];
    __syncthreads();
    int li = tid >> 4, n2 = tid & 15;
    size_t o = (size_t)bk * LL * NST + (size_t)(l0 + li) * NST + n2;
    g_Bt[o] = sB[n2][li];
    g_Ct[o] = sC[n2][li];
}

// ---------------- scan pass 1: per-chunk transforms (E,F) ----------------
__global__ void scan_pass1(const float* __restrict__ A_log)
{
    int bk = blockIdx.z;
    int k = bk & 3;
    int b = bk >> 2;
    int gch = blockIdx.y;
    int c = blockIdx.x * 16 + (threadIdx.x >> 4);
    int n = threadIdx.x & 15;

    float A = -__expf(A_log[(size_t)(k * CH + c) * NST + n]);
    const float* __restrict__ dp;
    const float* __restrict__ up;
    if (k & 1) {
        dp = g_dT + ((size_t)(b * 2 + (k >> 1)) * CH + c) * LL;
        up = g_xcT + (size_t)(b * CH + c) * LL;
    } else {
        dp = g_delta + (size_t)(bk * CH + c) * LL;
        up = g_xc + (size_t)(b * CH + c) * LL;
    }
    int rev = (k & 2);
    const float* __restrict__ Bp = g_Bt + (size_t)bk * LL * NST;
    int l0 = gch * CHUNK;

    float E = 1.f, F = 0.f;
#pragma unroll 4
    for (int i = 0; i < CHUNK; i++) {
        int l = l0 + i;
        int ml = rev ? (LL - 1 - l) : l;
        float dl = dp[ml];
        float uu = up[ml];
        float Bv = Bp[(size_t)l * NST + n];
        float e = __expf(dl * A);
        F = fmaf(e, F, dl * uu * Bv);
        E *= e;
    }
    size_t o = (size_t)((bk * CH + c) * NCHUNK + gch) * 2 * NST + n;
    g_EF[o] = E;
    g_EF[o + NST] = F;
}

// ---------------- scan pass 2: prefix + replay + mapped y write ----------------
__global__ void scan_pass2(const float* __restrict__ A_log, const float* __restrict__ Ds)
{
    __shared__ float y_s[16 * 257];
    int bk = blockIdx.z;
    int k = bk & 3;
    int b = bk >> 2;
    int gch = blockIdx.y;
    int grp = threadIdx.x >> 4;
    int c = blockIdx.x * 16 + grp;
    int n = threadIdx.x & 15;

    float A = -__expf(A_log[(size_t)(k * CH + c) * NST + n]);
    float D = Ds[k * CH + c];
    const float* __restrict__ dp;
    const float* __restrict__ up;
    if (k & 1) {
        dp = g_dT + ((size_t)(b * 2 + (k >> 1)) * CH + c) * LL;
        up = g_xcT + (size_t)(b * CH + c) * LL;
    } else {
        dp = g_delta + (size_t)(bk * CH + c) * LL;
        up = g_xc + (size_t)(b * CH + c) * LL;
    }
    int rev = (k & 2);
    const float* __restrict__ Bp = g_Bt + (size_t)bk * LL * NST;
    const float* __restrict__ Cp = g_Ct + (size_t)bk * LL * NST;
    int l0 = gch * CHUNK;

    float h = 0.f;
    const float* efp = g_EF + (size_t)(bk * CH + c) * NCHUNK * 2 * NST + n;
    for (int j = 0; j < gch; j++) {
        float Ej = efp[(size_t)j * 2 * NST];
        float Fj = efp[(size_t)j * 2 * NST + NST];
        h = fmaf(Ej, h, Fj);
    }

#pragma unroll 4
    for (int i = 0; i < CHUNK; i++) {
        int l = l0 + i;
        int ml = rev ? (LL - 1 - l) : l;
        float dl = dp[ml];
        float uu = up[ml];
        float Bv = Bp[(size_t)l * NST + n];
        float Cv = Cp[(size_t)l * NST + n];
        float e = __expf(dl * A);
        h = fmaf(e, h, dl * uu * Bv);
        float tt = h * Cv;
#pragma unroll
        for (int off = 1; off < 16; off <<= 1)
            tt += __shfl_xor_sync(0xffffffffu, tt, off);
        if (n == 0) y_s[grp * 257 + i] = tt + D * uu;
    }
    __syncthreads();

    float* yout = g_ys + (size_t)(bk * CH + blockIdx.x * 16) * LL;
    int tid = threadIdx.x;
    if ((k & 1) == 0) {
        for (int idx = tid; idx < 16 * 256; idx += 256) {
            int cl = idx >> 8, i = idx & 255;
            int tgt = mapk(k, l0 + i);
            yout[(size_t)cl * LL + tgt] = y_s[cl * 257 + i];
        }
    } else {
        for (int idx = tid; idx < 16 * 256; idx += 256) {
            int cl = idx >> 8;
            int rem = idx & 255;
            int hh = rem >> 2, j = rem & 3;
            int sl = j * 64 + hh;
            int tgt = mapk(k, l0 + sl);
            yout[(size_t)cl * LL + tgt] = y_s[cl * 257 + sl];
        }
    }
}

// ---------------- LayerNorm over channel + combine(4 dirs) + silu(z) gate ----------------
__global__ void ln_gate_kernel(const float* __restrict__ ln_g, const float* __restrict__ ln_b)
{
    __shared__ float sY[CH * 33];
    __shared__ float sZ[CH * 33];
    int b = blockIdx.y;
    int l0 = blockIdx.x * 32;
    int tid = threadIdx.x;
    const float* y0p = g_ys + (size_t)(b * KD + 0) * CH * LL;
    const float* y1p = g_ys + (size_t)(b * KD + 1) * CH * LL;
    const float* y2p = g_ys + (size_t)(b * KD + 2) * CH * LL;
    const float* y3p = g_ys + (size_t)(b * KD + 3) * CH * LL;
    const float* zp = g_xz + ((size_t)b * FGC + CH) * LL;
    for (int i = tid; i < CH * 32; i += 256) {
        int cc = i >> 5, ii = i & 31;
        size_t o = (size_t)cc * LL + l0 + ii;
        sY[cc * 33 + ii] = y0p[o] + y1p[o] + y2p[o] + y3p[o];
        sZ[cc * 33 + ii] = zp[o];
    }
    __syncthreads();
    int warp = tid >> 5, lane = tid & 31;
    float g0 = ln_g[lane], g1 = ln_g[lane + 32], g2 = ln_g[lane + 64];
    float bb0 = ln_b[lane], bb1 = ln_b[lane + 32], bb2 = ln_b[lane + 64];
    for (int q = 0; q < 4; q++) {
        int i = warp * 4 + q;
        float y0 = sY[lane * 33 + i], y1 = sY[(lane + 32) * 33 + i], y2 = sY[(lane + 64) * 33 + i];
        float s = y0 + y1 + y2;
        float ss = y0 * y0 + y1 * y1 + y2 * y2;
#pragma unroll
        for (int off = 16; off; off >>= 1) {
            s += __shfl_xor_sync(0xffffffffu, s, off);
            ss += __shfl_xor_sync(0xffffffffu, ss, off);
        }
        float mean = s * (1.f / 96.f);
        float var = ss * (1.f / 96.f) - mean * mean;
        float rs = rsqrtf(var + 1e-5f);
        float z0 = sZ[lane * 33 + i], z1 = sZ[(lane + 32) * 33 + i], z2 = sZ[(lane + 64) * 33 + i];
        float r0 = ((y0 - mean) * rs * g0 + bb0) * siluf(z0);
        float r1 = ((y1 - mean) * rs * g1 + bb1) * siluf(z1);
        float r2 = ((y2 - mean) * rs * g2 + bb2) * siluf(z2);
        sY[lane * 33 + i] = r0;
        sY[(lane + 32) * 33 + i] = r1;
        sY[(lane + 64) * 33 + i] = r2;
    }
    __syncthreads();
    float* op = g_yln + (size_t)b * CH * LL;
    for (int i = tid; i < CH * 32; i += 256) {
        int cc = i >> 5, ii = i & 31;
        op[(size_t)cc * LL + l0 + ii] = sY[cc * 33 + ii];
    }
}

// ---------------- psi gate: sigmoid(bn(conv1x1(relu(y)))) ----------------
__global__ void psi_kernel(const float* __restrict__ psi_w, const float* __restrict__ psi_b,
                           const float* __restrict__ psi_bn)
{
    int idx = blockIdx.x * blockDim.x + threadIdx.x;
    if (idx >= BB * LL) return;
    int b = idx / LL, l = idx % LL;
    const float* yp = g_y + (size_t)b * CH * LL + l;
    float acc = psi_b[0];
#pragma unroll 4
    for (int cc = 0; cc < CH; cc++)
        acc = fmaf(psi_w[cc], fmaxf(yp[(size_t)cc * LL], 0.f), acc);
    float s = psi_bn[0] * rsqrtf(psi_bn[3] + 1e-5f);
    float v = (acc - psi_bn[2]) * s + psi_bn[1];
    g_p[idx] = 1.f / (1.f + __expf(-v));
}

// ---------------- final: out = p*x + relu(ss) ----------------
__global__ void final_kernel(const float* __restrict__ x, float* __restrict__ out)
{
    int i4 = blockIdx.x * blockDim.x + threadIdx.x;
    if (i4 >= BB * CH * LL / 4) return;
    int idx = i4 * 4;
    int b = idx / (CH * LL);
    int l = idx % LL;
    float4 xv = *reinterpret_cast<const float4*>(x + idx);
    float4 sv = *reinterpret_cast<const float4*>(g_ss + idx);
    float4 pv = *reinterpret_cast<const float4*>(g_p + (size_t)b * LL + l);
    float4 o;
    o.x = pv.x * xv.x + fmaxf(sv.x, 0.f);
    o.y = pv.y * xv.y + fmaxf(sv.y, 0.f);
    o.z = pv.z * xv.z + fmaxf(sv.z, 0.f);
    o.w = pv.w * xv.w + fmaxf(sv.w, 0.f);
    *reinterpret_cast<float4*>(out + idx) = o;
}

// ---------------- host launch ----------------
extern "C" void kernel_launch(void* const* d_in, const int* in_sizes, int n_in,
                              void* d_out, int out_size)
{
    const float* g        = (const float*)d_in[0];
    const float* x        = (const float*)d_in[1];
    const float* wg_w     = (const float*)d_in[2];
    const float* wg_b     = (const float*)d_in[3];
    const float* wx_w     = (const float*)d_in[4];
    const float* wx_b     = (const float*)d_in[5];
    const float* psi_w    = (const float*)d_in[6];
    const float* psi_b    = (const float*)d_in[7];
    const float* psi_bn   = (const float*)d_in[8];
    const float* lk_w     = (const float*)d_in[9];
    const float* lk_bn    = (const float*)d_in[10];
    const float* br0      = (const float*)d_in[11];
    const float* br1      = (const float*)d_in[12];
    const float* br2      = (const float*)d_in[13];
    const float* br3      = (const float*)d_in[14];
    const float* br4      = (const float*)d_in[15];
    const float* br_bn    = (const float*)d_in[16];
    const float* in_proj_w= (const float*)d_in[17];
    const float* dw_w     = (const float*)d_in[18];
    const float* dw_b     = (const float*)d_in[19];
    const float* xproj_w  = (const float*)d_in[20];
    const float* dtproj_w = (const float*)d_in[21];
    const float* dtproj_b = (const float*)d_in[22];
    const float* A_log    = (const float*)d_in[23];
    const float* Ds       = (const float*)d_in[24];
    const float* ln_g     = (const float*)d_in[25];
    const float* ln_b     = (const float*)d_in[26];
    const float* outp_w   = (const float*)d_in[27];

    float *py, *pdr, *pxz, *pxc, *pdbl, *pdelta, *pyln, *pss;
    cudaGetSymbolAddress((void**)&py, g_y);
    cudaGetSymbolAddress((void**)&pdr, g_dr);
    cudaGetSymbolAddress((void**)&pxz, g_xz);
    cudaGetSymbolAddress((void**)&pxc, g_xc);
    cudaGetSymbolAddress((void**)&pdbl, g_dbl);
    cudaGetSymbolAddress((void**)&pdelta, g_delta);
    cudaGetSymbolAddress((void**)&pyln, g_yln);
    cudaGetSymbolAddress((void**)&pss, g_ss);

    // 1: y = conv1x1(g) + conv1x1(x)   (fused two-phase tiled GEMM)
    gemm_tiled<<<dim3(LL / PXB, CH / COB, BB), 256>>>(
        g, (size_t)FGC * LL, FGC, wg_w,
        x, (size_t)CH * LL, CH, wx_w,
        wg_b, wx_b, py, (size_t)CH * LL, CH, 0, 0);
    // 2: fused 6 depthwise convs + BN -> dr
    dwconv6_kernel<<<dim3(2, 2, BB * CH), dim3(32, 8)>>>(lk_w, lk_bn, br0, br1, br2, br3, br4, br_bn);
    // 3: in_proj -> xz
    gemm_tiled<<<dim3(LL / PXB, FGC / COB, BB), 256>>>(
        pdr, (size_t)CH * LL, CH, in_proj_w,
        nullptr, 0, 0, nullptr,
        nullptr, nullptr, pxz, (size_t)FGC * LL, FGC, 0, 0);
    // 4: depthwise 3x3 + silu -> xc
    dwconv3_silu_kernel<<<dim3(1, 8, BB * CH), dim3(64, 8)>>>(dw_w, dw_b);
    // 5: xproj -> dbl (per-direction weights, shared hw-order input)
    gemm_tiled<<<dim3(LL / PXB, (DBLR + COB - 1) / COB, BB * KD), 256>>>(
        pxc, (size_t)CH * LL, CH, xproj_w,
        nullptr, 0, 0, nullptr,
        nullptr, nullptr, pdbl, (size_t)DBLR * LL, DBLR, 1, 2);
    // 6: repack B/C into scan-order [l][n]
    repack_kernel<<<dim3(LL / 32, BB * KD), 512>>>();
    // 7: dtproj + softplus -> delta (hw order)
    gemm_pw<<<dim3(16, 24, BB * KD), 64, 4 * 6 * 4>>>(pdbl, (size_t)DBLR * LL, dtproj_w, dtproj_b,
                                                      pdelta, (size_t)CH * LL, CH, RKN, 1, 1, 0, 0);
    // 8: transpose xc and odd-direction delta planes
    transpose_kernel<<<BB * CH + 4 * CH, 256>>>();
    // 9-10: selective scan
    scan_pass1<<<dim3(CH / 16, NCHUNK, BB * KD), 256>>>(A_log);
    scan_pass2<<<dim3(CH / 16, NCHUNK, BB * KD), 256>>>(A_log, Ds);
    // 11: LN + combine + silu gate
    ln_gate_kernel<<<dim3(LL / 32, BB), 256>>>(ln_g, ln_b);
    // 12: out_proj -> ss
    gemm_tiled<<<dim3(LL / PXB, CH / COB, BB), 256>>>(
        pyln, (size_t)CH * LL, CH, outp_w,
        nullptr, 0, 0, nullptr,
        nullptr, nullptr, pss, (size_t)CH * LL, CH, 0, 0);
    // 13: psi gate
    psi_kernel<<<(BB * LL + 255) / 256, 256>>>(psi_w, psi_b, psi_bn);
    // 14: final
    final_kernel<<<(BB * CH * LL / 4 + 255) / 256, 256>>>(x, (float*)d_out);
}

// round 8
// speedup vs baseline: 4.6636x; 1.0173x over previous
#include <cuda_runtime.h>
#include <math.h>

#define BB 2
#define CH 96
#define FGC 192
#define HH 64
#define WW 64
#define LL 4096
#define NST 16
#define RKN 6
#define KD 4
#define DBLR 38
#define CHUNK 256
#define NCHUNK 16
#define PXB 128
#define KS 32

// ---------------- scratch (static device globals; no allocations) ----------------
__device__ float g_y[BB*CH*LL];
__device__ float g_dr[BB*CH*LL];
__device__ float g_xz[BB*2*CH*LL];
__device__ float g_xc[BB*CH*LL];
__device__ float g_xcT[BB*CH*LL];
__device__ float g_dbl[BB*KD*DBLR*LL];
__device__ float g_Bt[BB*KD*LL*NST];
__device__ float g_Ct[BB*KD*LL*NST];
__device__ float g_delta[BB*KD*CH*LL];
__device__ float g_dT[BB*2*CH*LL];
__device__ float g_ys[BB*KD*CH*LL];
__device__ float g_EF[BB*KD*CH*NCHUNK*2*NST];
__device__ float g_yln[BB*CH*LL];
__device__ float g_ss[BB*CH*LL];

__device__ __forceinline__ float softplusf(float x) {
    return (x > 20.f) ? x : log1pf(__expf(x));
}
__device__ __forceinline__ float siluf(float x) {
    return x / (1.f + __expf(-x));
}
// scan-order l -> hw-order index for direction k
__device__ __forceinline__ int mapk(int k, int l) {
    int l2 = (k & 2) ? (4095 - l) : l;
    return (k & 1) ? (((l2 & 63) << 6) | (l2 >> 6)) : l2;
}

// ---------------- smem-tiled GEMM, register-blocked ----------------
// thread: COPT outputs x 4 pixels. block 256 = 32 px-quads x 8 co-groups.
// COB = COPT*8 outputs, PXB=128 pixels per block. Two-phase K (A then B).
template<int COPT>
__global__ void gemm_tiled(const float* __restrict__ inA, size_t strideA, int K1,
                           const float* __restrict__ WA,
                           const float* __restrict__ inB, size_t strideB, int K2,
                           const float* __restrict__ WB,
                           const float* __restrict__ bias1, const float* __restrict__ bias2,
                           float* __restrict__ out, size_t outStride,
                           int M, int perBatchW, int inShift)
{
    const int COB = COPT * 8;
    __shared__ float sIn[KS * PXB];   // 16 KB
    __shared__ float sW[COPT * 8 * KS];
    int bb = blockIdx.z;
    int ib = bb >> inShift;
    int wsel = perBatchW ? (bb & 3) : 0;
    int px0 = blockIdx.x * PXB;
    int co0 = blockIdx.y * COB;
    int tid = threadIdx.x;
    int quad = tid & 31;
    int cog = tid >> 5;

    float4 acc[COPT];
#pragma unroll
    for (int j = 0; j < COPT; j++) acc[j] = make_float4(0.f, 0.f, 0.f, 0.f);

    int nslice = (K1 + K2) / KS;
    for (int s = 0; s < nslice; s++) {
        int ks = s * KS;
        const float* ip;
        const float* wp;
        int kbase, KKcur;
        if (ks < K1) {
            ip = inA + (size_t)ib * strideA;
            wp = WA + (size_t)wsel * M * K1;
            kbase = ks; KKcur = K1;
        } else {
            ip = inB + (size_t)ib * strideB;
            wp = WB;
            kbase = ks - K1; KKcur = K2;
        }
        // stage input slice: KS rows x PXB px = 1024 float4, 4 per thread
#pragma unroll
        for (int t = 0; t < 4; t++) {
            int idx = tid + t * 256;
            int row = idx >> 5, c4 = idx & 31;
            *reinterpret_cast<float4*>(&sIn[row * PXB + c4 * 4]) =
                *reinterpret_cast<const float4*>(ip + (size_t)(kbase + row) * LL + px0 + c4 * 4);
        }
        // stage weight slice: COB rows x KS floats = COB*8 float4
        {
            int nw = COB * (KS / 4);
            if (tid < nw) {
                int r = tid >> 3, c4 = tid & 7;
                int co = co0 + r;
                float4 wv = make_float4(0.f, 0.f, 0.f, 0.f);
                if (co < M)
                    wv = *reinterpret_cast<const float4*>(wp + (size_t)co * KKcur + kbase + c4 * 4);
                *reinterpret_cast<float4*>(&sW[r * KS + c4 * 4]) = wv;
            }
        }
        __syncthreads();
#pragma unroll
        for (int ci = 0; ci < KS; ci++) {
            float4 v = *reinterpret_cast<const float4*>(&sIn[ci * PXB + quad * 4]);
#pragma unroll
            for (int j = 0; j < COPT; j++) {
                float w = sW[(cog * COPT + j) * KS + ci];
                acc[j].x = fmaf(w, v.x, acc[j].x);
                acc[j].y = fmaf(w, v.y, acc[j].y);
                acc[j].z = fmaf(w, v.z, acc[j].z);
                acc[j].w = fmaf(w, v.w, acc[j].w);
            }
        }
        __syncthreads();
    }
#pragma unroll
    for (int j = 0; j < COPT; j++) {
        int co = co0 + cog * COPT + j;
        if (co >= M) continue;
        float bv = 0.f;
        if (bias1 != nullptr) bv += bias1[co];
        if (bias2 != nullptr) bv += bias2[co];
        float4 r = acc[j];
        r.x += bv; r.y += bv; r.z += bv; r.w += bv;
        *reinterpret_cast<float4*>(out + (size_t)bb * outStride + (size_t)co * LL + px0 + quad * 4) = r;
    }
}

// ---------------- small-K GEMM (dtproj: K=6) ----------------
__global__ void gemm_pw(const float* __restrict__ in, size_t inStride,
                        const float* __restrict__ W, const float* __restrict__ bias,
                        float* __restrict__ out, size_t outStride,
                        int M, int KK, int perBatchW, int act, int accum, int inShift)
{
    extern __shared__ float sW[];
    int bb = blockIdx.z;
    int wsel = perBatchW ? (bb & 3) : 0;
    int co0 = blockIdx.y * 4;
    const float* Wp = W + (size_t)wsel * M * KK;
    for (int i = threadIdx.x; i < 4 * KK; i += blockDim.x) {
        int co = co0 + i / KK;
        sW[i] = (co < M) ? Wp[(size_t)co * KK + (i % KK)] : 0.f;
    }
    __syncthreads();
    int pix = blockIdx.x * 256 + threadIdx.x * 4;
    const float* ip = in + (size_t)(bb >> inShift) * inStride + pix;
    float4 acc[4];
#pragma unroll
    for (int j = 0; j < 4; j++) {
        float bv = 0.f;
        if (bias != nullptr && (co0 + j) < M) bv = bias[wsel * M + co0 + j];
        acc[j] = make_float4(bv, bv, bv, bv);
    }
#pragma unroll 8
    for (int ci = 0; ci < KK; ci++) {
        float4 v = *reinterpret_cast<const float4*>(ip + (size_t)ci * LL);
#pragma unroll
        for (int j = 0; j < 4; j++) {
            float w = sW[j * KK + ci];
            acc[j].x = fmaf(w, v.x, acc[j].x);
            acc[j].y = fmaf(w, v.y, acc[j].y);
            acc[j].z = fmaf(w, v.z, acc[j].z);
            acc[j].w = fmaf(w, v.w, acc[j].w);
        }
    }
#pragma unroll
    for (int j = 0; j < 4; j++) {
        int co = co0 + j;
        if (co >= M) continue;
        float4 r = acc[j];
        if (act == 1) {
            r.x = softplusf(r.x); r.y = softplusf(r.y);
            r.z = softplusf(r.z); r.w = softplusf(r.w);
        }
        float* op = out + (size_t)bb * outStride + (size_t)co * LL + pix;
        if (accum) {
            float4 o = *reinterpret_cast<const float4*>(op);
            r.x += o.x; r.y += o.y; r.z += o.z; r.w += o.w;
        }
        *reinterpret_cast<float4*>(op) = r;
    }
}

// ---------------- fused 6x depthwise dilated conv + BN ----------------
__global__ void dwconv6_kernel(const float* __restrict__ lk_w, const float* __restrict__ lk_bn,
                               const float* __restrict__ b0w, const float* __restrict__ b1w,
                               const float* __restrict__ b2w, const float* __restrict__ b3w,
                               const float* __restrict__ b4w, const float* __restrict__ br_bn)
{
    __shared__ float sIn[44 * 44];
    __shared__ float sWt[270];
    int bc = blockIdx.z;
    int c = bc % CH;
    int h0 = blockIdx.y * 32;
    int w0 = blockIdx.x * 32;
    const float* in = g_y + (size_t)bc * LL;
    int tid = threadIdx.y * 32 + threadIdx.x;

    float s_lk = lk_bn[c] * rsqrtf(lk_bn[3 * CH + c] + 1e-5f);
    float sbr[5];
#pragma unroll
    for (int i = 0; i < 5; i++)
        sbr[i] = br_bn[(i * 4 + 0) * CH + c] * rsqrtf(br_bn[(i * 4 + 3) * CH + c] + 1e-5f);

    for (int i = tid; i < 270; i += 256) {
        float w;
        if (i < 169)      w = lk_w[c * 169 + i] * s_lk;
        else if (i < 194) w = b0w[c * 25 + (i - 169)] * sbr[0];
        else if (i < 243) w = b1w[c * 49 + (i - 194)] * sbr[1];
        else if (i < 252) w = b2w[c * 9 + (i - 243)] * sbr[2];
        else if (i < 261) w = b3w[c * 9 + (i - 252)] * sbr[3];
        else              w = b4w[c * 9 + (i - 261)] * sbr[4];
        sWt[i] = w;
    }
    for (int i = tid; i < 44 * 44; i += 256) {
        int r = i / 44, cl = i % 44;
        int gh = h0 - 6 + r, gw = w0 - 6 + cl;
        float v = 0.f;
        if (gh >= 0 && gh < HH && gw >= 0 && gw < WW) v = in[gh * WW + gw];
        sIn[i] = v;
    }
    __syncthreads();

    int tx = threadIdx.x, ty = threadIdx.y;
    float a0 = 0.f, a1 = 0.f, a2 = 0.f, a3 = 0.f;
    const float* base = sIn + (ty + 6) * 44 + (tx + 6);

#pragma unroll 1
    for (int ky = 0; ky < 13; ky++) {
        const float* rp = base + (ky - 6) * 44;
#pragma unroll
        for (int kx = 0; kx < 13; kx++) {
            float w = sWt[ky * 13 + kx];
            int dx = kx - 6;
            a0 = fmaf(w, rp[dx], a0);
            a1 = fmaf(w, rp[dx + 352], a1);
            a2 = fmaf(w, rp[dx + 704], a2);
            a3 = fmaf(w, rp[dx + 1056], a3);
        }
    }
#define BRANCH(KSZ, DIL, OFF) \
    { const int hk = (KSZ - 1) / 2; \
      _Pragma("unroll 1") \
      for (int ky = 0; ky < KSZ; ky++) { \
          const float* rp = base + (ky - hk) * DIL * 44; \
          _Pragma("unroll") \
          for (int kx = 0; kx < KSZ; kx++) { \
              float w = sWt[OFF + ky * KSZ + kx]; \
              int dx = (kx - hk) * DIL; \
              a0 = fmaf(w, rp[dx], a0); \
              a1 = fmaf(w, rp[dx + 352], a1); \
              a2 = fmaf(w, rp[dx + 704], a2); \
              a3 = fmaf(w, rp[dx + 1056], a3); \
          } } }
    BRANCH(5, 1, 169)
    BRANCH(7, 2, 194)
    BRANCH(3, 3, 243)
    BRANCH(3, 4, 252)
    BRANCH(3, 5, 261)
#undef BRANCH

    float T = lk_bn[CH + c] - lk_bn[2 * CH + c] * s_lk;
#pragma unroll
    for (int i = 0; i < 5; i++)
        T += br_bn[(i * 4 + 1) * CH + c] - br_bn[(i * 4 + 2) * CH + c] * sbr[i];

    float* op = g_dr + (size_t)bc * LL;
    op[(h0 + ty + 0) * WW + w0 + tx]  = a0 + T;
    op[(h0 + ty + 8) * WW + w0 + tx]  = a1 + T;
    op[(h0 + ty + 16) * WW + w0 + tx] = a2 + T;
    op[(h0 + ty + 24) * WW + w0 + tx] = a3 + T;
}

// ---------------- 3x3 depthwise conv + bias + silu on xp ----------------
__global__ void dwconv3_silu_kernel(const float* __restrict__ dw_w, const float* __restrict__ dw_b)
{
    __shared__ float sIn[10 * 66];
    int bc = blockIdx.z;
    int c = bc % CH;
    int b = bc / CH;
    int h0 = blockIdx.y * 8;
    const float* in = g_xz + ((size_t)b * FGC + c) * LL;
    int tid = threadIdx.y * 64 + threadIdx.x;
    for (int i = tid; i < 10 * 66; i += 512) {
        int r = i / 66, cl = i % 66;
        int gh = h0 - 1 + r, gw = -1 + cl;
        sIn[i] = (gh >= 0 && gh < HH && gw >= 0 && gw < WW) ? in[gh * WW + gw] : 0.f;
    }
    float wreg[9];
#pragma unroll
    for (int i = 0; i < 9; i++) wreg[i] = dw_w[c * 9 + i];
    __syncthreads();
    int tx = threadIdx.x, ty = threadIdx.y;
    float a = dw_b[c];
#pragma unroll
    for (int ky = 0; ky < 3; ky++)
#pragma unroll
        for (int kx = 0; kx < 3; kx++)
            a = fmaf(wreg[ky * 3 + kx], sIn[(ty + ky) * 66 + tx + kx], a);
    g_xc[(size_t)bc * LL + (h0 + ty) * WW + tx] = siluf(a);
}

// ---------------- transpose 64x64 planes: xc -> xcT, delta(odd k) -> dT ----------------
__global__ void transpose_kernel()
{
    __shared__ float s[64][65];
    int p = blockIdx.x;
    const float* in;
    float* out;
    if (p < BB * CH) {
        in = g_xc + (size_t)p * LL;
        out = g_xcT + (size_t)p * LL;
    } else {
        int q = p - BB * CH;
        int j = q / CH;
        int c = q % CH;
        int b = j >> 1;
        int kk = (j & 1) ? 3 : 1;
        in = g_delta + ((size_t)(b * KD + kk) * CH + c) * LL;
        out = g_dT + ((size_t)(b * 2 + (j & 1)) * CH + c) * LL;
    }
    int tid = threadIdx.x;
    for (int i = tid; i < 4096; i += 256) {
        s[i >> 6][i & 63] = in[i];
    }
    __syncthreads();
    for (int i = tid; i < 4096; i += 256) {
        out[i] = s[i & 63][i >> 6];
    }
}

// ---------------- repack B/C rows of dbl into scan-order [l][n] ----------------
__global__ void repack_kernel()
{
    __shared__ float sB[16][33], sC[16][33];
    int bk = blockIdx.y;
    int k = bk & 3;
    int l0 = blockIdx.x * 32;
    int tid = threadIdx.x;
    int n = tid >> 5, i = tid & 31;
    const float* dp = g_dbl + (size_t)bk * DBLR * LL;
    int ml = mapk(k, l0 + i);
    sB[n][i] = dp[(size_t)(RKN + n) * LL + ml];
    sC[n][i] = dp[(size_t)(RKN + NST + n) * LL + ml];
    __syncthreads();
    int li = tid >> 4, n2 = tid & 15;
    size_t o = (size_t)bk * LL * NST + (size_t)(l0 + li) * NST + n2;
    g_Bt[o] = sB[n2][li];
    g_Ct[o] = sC[n2][li];
}

// ---------------- scan pass 1: per-chunk transforms (E,F) ----------------
__global__ void scan_pass1(const float* __restrict__ A_log)
{
    int bk = blockIdx.z;
    int k = bk & 3;
    int b = bk >> 2;
    int gch = blockIdx.y;
    int c = blockIdx.x * 16 + (threadIdx.x >> 4);
    int n = threadIdx.x & 15;

    float A = -__expf(A_log[(size_t)(k * CH + c) * NST + n]);
    const float* __restrict__ dp;
    const float* __restrict__ up;
    if (k & 1) {
        dp = g_dT + ((size_t)(b * 2 + (k >> 1)) * CH + c) * LL;
        up = g_xcT + (size_t)(b * CH + c) * LL;
    } else {
        dp = g_delta + (size_t)(bk * CH + c) * LL;
        up = g_xc + (size_t)(b * CH + c) * LL;
    }
    int rev = (k & 2);
    const float* __restrict__ Bp = g_Bt + (size_t)bk * LL * NST;
    int l0 = gch * CHUNK;

    float E = 1.f, F = 0.f;
#pragma unroll 4
    for (int i = 0; i < CHUNK; i++) {
        int l = l0 + i;
        int ml = rev ? (LL - 1 - l) : l;
        float dl = dp[ml];
        float uu = up[ml];
        float Bv = Bp[(size_t)l * NST + n];
        float e = __expf(dl * A);
        F = fmaf(e, F, dl * uu * Bv);
        E *= e;
    }
    size_t o = (size_t)((bk * CH + c) * NCHUNK + gch) * 2 * NST + n;
    g_EF[o] = E;
    g_EF[o + NST] = F;
}

// ---------------- scan pass 2: prefix + replay + mapped y write ----------------
__global__ void scan_pass2(const float* __restrict__ A_log, const float* __restrict__ Ds)
{
    __shared__ float y_s[16 * 257];
    int bk = blockIdx.z;
    int k = bk & 3;
    int b = bk >> 2;
    int gch = blockIdx.y;
    int grp = threadIdx.x >> 4;
    int c = blockIdx.x * 16 + grp;
    int n = threadIdx.x & 15;

    float A = -__expf(A_log[(size_t)(k * CH + c) * NST + n]);
    float D = Ds[k * CH + c];
    const float* __restrict__ dp;
    const float* __restrict__ up;
    if (k & 1) {
        dp = g_dT + ((size_t)(b * 2 + (k >> 1)) * CH + c) * LL;
        up = g_xcT + (size_t)(b * CH + c) * LL;
    } else {
        dp = g_delta + (size_t)(bk * CH + c) * LL;
        up = g_xc + (size_t)(b * CH + c) * LL;
    }
    int rev = (k & 2);
    const float* __restrict__ Bp = g_Bt + (size_t)bk * LL * NST;
    const float* __restrict__ Cp = g_Ct + (size_t)bk * LL * NST;
    int l0 = gch * CHUNK;

    float h = 0.f;
    const float* efp = g_EF + (size_t)(bk * CH + c) * NCHUNK * 2 * NST + n;
    for (int j = 0; j < gch; j++) {
        float Ej = efp[(size_t)j * 2 * NST];
        float Fj = efp[(size_t)j * 2 * NST + NST];
        h = fmaf(Ej, h, Fj);
    }

#pragma unroll 4
    for (int i = 0; i < CHUNK; i++) {
        int l = l0 + i;
        int ml = rev ? (LL - 1 - l) : l;
        float dl = dp[ml];
        float uu = up[ml];
        float Bv = Bp[(size_t)l * NST + n];
        float Cv = Cp[(size_t)l * NST + n];
        float e = __expf(dl * A);
        h = fmaf(e, h, dl * uu * Bv);
        float tt = h * Cv;
#pragma unroll
        for (int off = 1; off < 16; off <<= 1)
            tt += __shfl_xor_sync(0xffffffffu, tt, off);
        if (n == 0) y_s[grp * 257 + i] = tt + D * uu;
    }
    __syncthreads();

    float* yout = g_ys + (size_t)(bk * CH + blockIdx.x * 16) * LL;
    int tid = threadIdx.x;
    if ((k & 1) == 0) {
        for (int idx = tid; idx < 16 * 256; idx += 256) {
            int cl = idx >> 8, i = idx & 255;
            int tgt = mapk(k, l0 + i);
            yout[(size_t)cl * LL + tgt] = y_s[cl * 257 + i];
        }
    } else {
        for (int idx = tid; idx < 16 * 256; idx += 256) {
            int cl = idx >> 8;
            int rem = idx & 255;
            int hh = rem >> 2, j = rem & 3;
            int sl = j * 64 + hh;
            int tgt = mapk(k, l0 + sl);
            yout[(size_t)cl * LL + tgt] = y_s[cl * 257 + sl];
        }
    }
}

// ---------------- LayerNorm over channel + combine(4 dirs) + silu(z) gate ----------------
__global__ void ln_gate_kernel(const float* __restrict__ ln_g, const float* __restrict__ ln_b)
{
    __shared__ float sY[CH * 33];
    __shared__ float sZ[CH * 33];
    int b = blockIdx.y;
    int l0 = blockIdx.x * 32;
    int tid = threadIdx.x;
    const float* y0p = g_ys + (size_t)(b * KD + 0) * CH * LL;
    const float* y1p = g_ys + (size_t)(b * KD + 1) * CH * LL;
    const float* y2p = g_ys + (size_t)(b * KD + 2) * CH * LL;
    const float* y3p = g_ys + (size_t)(b * KD + 3) * CH * LL;
    const float* zp = g_xz + ((size_t)b * FGC + CH) * LL;
    for (int i = tid; i < CH * 32; i += 256) {
        int cc = i >> 5, ii = i & 31;
        size_t o = (size_t)cc * LL + l0 + ii;
        sY[cc * 33 + ii] = y0p[o] + y1p[o] + y2p[o] + y3p[o];
        sZ[cc * 33 + ii] = zp[o];
    }
    __syncthreads();
    int warp = tid >> 5, lane = tid & 31;
    float g0 = ln_g[lane], g1 = ln_g[lane + 32], g2 = ln_g[lane + 64];
    float bb0 = ln_b[lane], bb1 = ln_b[lane + 32], bb2 = ln_b[lane + 64];
    for (int q = 0; q < 4; q++) {
        int i = warp * 4 + q;
        float y0 = sY[lane * 33 + i], y1 = sY[(lane + 32) * 33 + i], y2 = sY[(lane + 64) * 33 + i];
        float s = y0 + y1 + y2;
        float ss = y0 * y0 + y1 * y1 + y2 * y2;
#pragma unroll
        for (int off = 16; off; off >>= 1) {
            s += __shfl_xor_sync(0xffffffffu, s, off);
            ss += __shfl_xor_sync(0xffffffffu, ss, off);
        }
        float mean = s * (1.f / 96.f);
        float var = ss * (1.f / 96.f) - mean * mean;
        float rs = rsqrtf(var + 1e-5f);
        float z0 = sZ[lane * 33 + i], z1 = sZ[(lane + 32) * 33 + i], z2 = sZ[(lane + 64) * 33 + i];
        float r0 = ((y0 - mean) * rs * g0 + bb0) * siluf(z0);
        float r1 = ((y1 - mean) * rs * g1 + bb1) * siluf(z1);
        float r2 = ((y2 - mean) * rs * g2 + bb2) * siluf(z2);
        sY[lane * 33 + i] = r0;
        sY[(lane + 32) * 33 + i] = r1;
        sY[(lane + 64) * 33 + i] = r2;
    }
    __syncthreads();
    float* op = g_yln + (size_t)b * CH * LL;
    for (int i = tid; i < CH * 32; i += 256) {
        int cc = i >> 5, ii = i & 31;
        op[(size_t)cc * LL + l0 + ii] = sY[cc * 33 + ii];
    }
}

// ---------------- fused psi gate + final: out = sigmoid(bn(psi(relu(y))))*x + relu(ss) ----------------
__global__ void psi_final_kernel(const float* __restrict__ x,
                                 const float* __restrict__ psi_w, const float* __restrict__ psi_b,
                                 const float* __restrict__ psi_bn, float* __restrict__ out)
{
    int b = blockIdx.y;
    int l = blockIdx.x * 256 + threadIdx.x;
    const float* yp = g_y + (size_t)b * CH * LL + l;
    float acc = psi_b[0];
#pragma unroll 8
    for (int cc = 0; cc < CH; cc++)
        acc = fmaf(psi_w[cc], fmaxf(yp[(size_t)cc * LL], 0.f), acc);
    float s = psi_bn[0] * rsqrtf(psi_bn[3] + 1e-5f);
    float v = (acc - psi_bn[2]) * s + psi_bn[1];
    float p = 1.f / (1.f + __expf(-v));

    const float* xp = x + (size_t)b * CH * LL + l;
    const float* sp = g_ss + (size_t)b * CH * LL + l;
    float* op = out + (size_t)b * CH * LL + l;
#pragma unroll 8
    for (int cc = 0; cc < CH; cc++) {
        size_t o = (size_t)cc * LL;
        op[o] = p * xp[o] + fmaxf(sp[o], 0.f);
    }
}

// ---------------- host launch ----------------
extern "C" void kernel_launch(void* const* d_in, const int* in_sizes, int n_in,
                              void* d_out, int out_size)
{
    const float* g        = (const float*)d_in[0];
    const float* x        = (const float*)d_in[1];
    const float* wg_w     = (const float*)d_in[2];
    const float* wg_b     = (const float*)d_in[3];
    const float* wx_w     = (const float*)d_in[4];
    const float* wx_b     = (const float*)d_in[5];
    const float* psi_w    = (const float*)d_in[6];
    const float* psi_b    = (const float*)d_in[7];
    const float* psi_bn   = (const float*)d_in[8];
    const float* lk_w     = (const float*)d_in[9];
    const float* lk_bn    = (const float*)d_in[10];
    const float* br0      = (const float*)d_in[11];
    const float* br1      = (const float*)d_in[12];
    const float* br2      = (const float*)d_in[13];
    const float* br3      = (const float*)d_in[14];
    const float* br4      = (const float*)d_in[15];
    const float* br_bn    = (const float*)d_in[16];
    const float* in_proj_w= (const float*)d_in[17];
    const float* dw_w     = (const float*)d_in[18];
    const float* dw_b     = (const float*)d_in[19];
    const float* xproj_w  = (const float*)d_in[20];
    const float* dtproj_w = (const float*)d_in[21];
    const float* dtproj_b = (const float*)d_in[22];
    const float* A_log    = (const float*)d_in[23];
    const float* Ds       = (const float*)d_in[24];
    const float* ln_g     = (const float*)d_in[25];
    const float* ln_b     = (const float*)d_in[26];
    const float* outp_w   = (const float*)d_in[27];

    float *py, *pdr, *pxz, *pxc, *pdbl, *pdelta, *pyln, *pss;
    cudaGetSymbolAddress((void**)&py, g_y);
    cudaGetSymbolAddress((void**)&pdr, g_dr);
    cudaGetSymbolAddress((void**)&pxz, g_xz);
    cudaGetSymbolAddress((void**)&pxc, g_xc);
    cudaGetSymbolAddress((void**)&pdbl, g_dbl);
    cudaGetSymbolAddress((void**)&pdelta, g_delta);
    cudaGetSymbolAddress((void**)&pyln, g_yln);
    cudaGetSymbolAddress((void**)&pss, g_ss);

    // 1: y = conv1x1(g) + conv1x1(x)  (fused two-phase tiled GEMM, 4co x 4px)
    gemm_tiled<4><<<dim3(LL / PXB, CH / 32, BB), 256>>>(
        g, (size_t)FGC * LL, FGC, wg_w,
        x, (size_t)CH * LL, CH, wx_w,
        wg_b, wx_b, py, (size_t)CH * LL, CH, 0, 0);
    // 2: fused 6 depthwise convs + BN -> dr
    dwconv6_kernel<<<dim3(2, 2, BB * CH), dim3(32, 8)>>>(lk_w, lk_bn, br0, br1, br2, br3, br4, br_bn);
    // 3: in_proj -> xz
    gemm_tiled<4><<<dim3(LL / PXB, FGC / 32, BB), 256>>>(
        pdr, (size_t)CH * LL, CH, in_proj_w,
        nullptr, 0, 0, nullptr,
        nullptr, nullptr, pxz, (size_t)FGC * LL, FGC, 0, 0);
    // 4: depthwise 3x3 + silu -> xc
    dwconv3_silu_kernel<<<dim3(1, 8, BB * CH), dim3(64, 8)>>>(dw_w, dw_b);
    // 5: xproj -> dbl (per-direction weights, shared hw-order input; M=38 -> COPT=2)
    gemm_tiled<2><<<dim3(LL / PXB, (DBLR + 15) / 16, BB * KD), 256>>>(
        pxc, (size_t)CH * LL, CH, xproj_w,
        nullptr, 0, 0, nullptr,
        nullptr, nullptr, pdbl, (size_t)DBLR * LL, DBLR, 1, 2);
    // 6: repack B/C into scan-order [l][n]
    repack_kernel<<<dim3(LL / 32, BB * KD), 512>>>();
    // 7: dtproj + softplus -> delta (hw order)
    gemm_pw<<<dim3(16, 24, BB * KD), 64, 4 * 6 * 4>>>(pdbl, (size_t)DBLR * LL, dtproj_w, dtproj_b,
                                                      pdelta, (size_t)CH * LL, CH, RKN, 1, 1, 0, 0);
    // 8: transpose xc and odd-direction delta planes
    transpose_kernel<<<BB * CH + 4 * CH, 256>>>();
    // 9-10: selective scan
    scan_pass1<<<dim3(CH / 16, NCHUNK, BB * KD), 256>>>(A_log);
    scan_pass2<<<dim3(CH / 16, NCHUNK, BB * KD), 256>>>(A_log, Ds);
    // 11: LN + combine + silu gate
    ln_gate_kernel<<<dim3(LL / 32, BB), 256>>>(ln_g, ln_b);
    // 12: out_proj -> ss
    gemm_tiled<4><<<dim3(LL / PXB, CH / 32, BB), 256>>>(
        pyln, (size_t)CH * LL, CH, outp_w,
        nullptr, 0, 0, nullptr,
        nullptr, nullptr, pss, (size_t)CH * LL, CH, 0, 0);
    // 13: fused psi + final
    psi_final_kernel<<<dim3(LL / 256, BB), 256>>>(x, psi_w, psi_b, psi_bn, (float*)d_out);
}